// round 13
// baseline (speedup 1.0000x reference)
#include <cuda_runtime.h>
#include <math.h>
#include <stdint.h>

#define BB   4
#define SSEQ 2048
#define DD   512
#define HH   8
#define DHH  64
#define E3   1536

// Scratch (allocation-free rule: __device__ globals)
__device__ float g_q[BB*HH*SSEQ*DHH];    // [b,h,s,dh]
__device__ float g_k[BB*HH*SSEQ*DHH];
__device__ float g_v[BB*HH*SSEQ*DHH];
__device__ float g_attn[BB*SSEQ*DD];     // [b,s,d]
__device__ int   g_cnt[BB];              // active-key count per batch
__device__ int   g_idx[BB*SSEQ];         // active key indices (unordered)

// ---------------------------------------------------------------------------
// TF32 mma.sync helpers (plain sm_80+ PTX)
// ---------------------------------------------------------------------------
__device__ __forceinline__ uint32_t f2tf32(float x) {
    uint32_t y;
    asm("cvt.rna.tf32.f32 %0, %1;" : "=r"(y) : "f"(x));
    return y;
}
// Register-time round-to-nearest for raw fp32 bits fed to tf32 MMA.
#define RNA(x) ((x) + 0x1000u)

__device__ __forceinline__ void mma_tf32(float (&d)[4], const uint32_t (&a)[4],
                                         const uint32_t (&b)[2]) {
    asm volatile("mma.sync.aligned.m16n8k8.row.col.f32.tf32.tf32.f32 "
                 "{%0,%1,%2,%3}, {%4,%5,%6,%7}, {%8,%9}, {%0,%1,%2,%3};"
                 : "+f"(d[0]), "+f"(d[1]), "+f"(d[2]), "+f"(d[3])
                 : "r"(a[0]), "r"(a[1]), "r"(a[2]), "r"(a[3]),
                   "r"(b[0]), "r"(b[1]));
}
__device__ __forceinline__ uint32_t smem_u32(const void* p) {
    uint32_t a;
    asm("{ .reg .u64 t; cvta.to.shared.u64 t, %1; cvt.u32.u64 %0, t; }"
        : "=r"(a) : "l"(p));
    return a;
}

// Fast 2^x for x <= 0 on the FMA pipe (no MUFU). Rel err ~4e-5.
__device__ __forceinline__ float fexp2(float x) {
    x = fmaxf(x, -126.0f);
    const float z = x + 12582912.0f;                       // 1.5*2^23
    const int   n = (__float_as_int(z) & 0x7FFFFF) - 0x400000;
    const float f = x - (z - 12582912.0f);
    float p = fmaf(fmaf(fmaf(fmaf(0.00961813f, f, 0.05550411f),
                             f, 0.24022651f), f, 0.69314718f), f, 1.0f);
    return __int_as_float(__float_as_int(p) + (n << 23));
}

// ---------------------------------------------------------------------------
// Projection GEMMs: 128x128 CTA tile, 8 warps (2M x 4N), warp tile 64x32.
// cp.async 3-stage pipeline with ONE barrier per chunk:
//   wait(ch) -> sync -> prefetch(ch+2) -> compute(ch).
// ---------------------------------------------------------------------------
#define GST 36
#define KC  32
#define NCH (DD/KC)          // 16 chunks
#define NST 3                // pipeline stages
#define GEMM_TILE_U32 (128*GST)
#define GEMM_SMEM_BYTES (NST * 2 * GEMM_TILE_U32 * 4)   // 110592

__device__ __forceinline__ void gemm_prefetch(const float* __restrict__ Ag,
                                              const float* __restrict__ Bg,
                                              int ch, uint32_t a_byte,
                                              uint32_t b_byte, int tid) {
    const uint32_t so = (uint32_t)((ch % NST) * 2 * GEMM_TILE_U32 * 4);
    #pragma unroll
    for (int it = 0; it < 4; it++) {
        const int i = tid + it * 256;
        const int r = i >> 3;               // row 0..127
        const int c = (i & 7) * 16;         // byte chunk within 128B row
        const void* ga = (const char*)(Ag + (size_t)r * DD + ch * KC) + c;
        const void* gb = (const char*)(Bg + (size_t)r * DD + ch * KC) + c;
        const uint32_t da = a_byte + so + (uint32_t)r * (GST*4) + c;
        const uint32_t db = b_byte + so + (uint32_t)r * (GST*4) + c;
        asm volatile("cp.async.cg.shared.global [%0], [%1], 16;" :: "r"(da), "l"(ga));
        asm volatile("cp.async.cg.shared.global [%0], [%1], 16;" :: "r"(db), "l"(gb));
    }
    asm volatile("cp.async.commit_group;" ::: "memory");
}

__device__ __forceinline__ void mma_mainloop(const float* __restrict__ Ag,
                                             const float* __restrict__ Bg,
                                             uint32_t* smu,
                                             float acc[4][4][4]) {
    const int tid = threadIdx.x;
    const int wid = tid >> 5, lane = tid & 31;
    const int wm = wid >> 2, wn = wid & 3;
    const int lr = lane >> 2, lc = lane & 3;
    const uint32_t sb = smem_u32(smu);
    const uint32_t a_byte = sb;
    const uint32_t b_byte = sb + GEMM_TILE_U32 * 4;

    gemm_prefetch(Ag, Bg, 0, a_byte, b_byte, tid);
    gemm_prefetch(Ag, Bg, 1, a_byte, b_byte, tid);

    for (int ch = 0; ch < NCH; ch++) {
        asm volatile("cp.async.wait_group 1;" ::: "memory");   // chunk ch landed
        __syncthreads();
        if (ch + 2 < NCH)
            gemm_prefetch(Ag, Bg, ch + 2, a_byte, b_byte, tid);
        else
            asm volatile("cp.async.commit_group;" ::: "memory");  // empty group

        const uint32_t* As = smu + (ch % NST) * 2 * GEMM_TILE_U32;
        const uint32_t* Bs = As + GEMM_TILE_U32;

        #pragma unroll
        for (int ks = 0; ks < KC; ks += 8) {
            uint32_t a[4][4], b[4][2];
            #pragma unroll
            for (int mf = 0; mf < 4; mf++) {
                const uint32_t* p = As + (wm*64 + mf*16 + lr) * GST + ks + lc;
                a[mf][0] = RNA(p[0]);
                a[mf][1] = RNA(p[8*GST]);
                a[mf][2] = RNA(p[4]);
                a[mf][3] = RNA(p[8*GST + 4]);
            }
            #pragma unroll
            for (int nf = 0; nf < 4; nf++) {
                const uint32_t* p = Bs + (wn*32 + nf*8 + lr) * GST + ks + lc;
                b[nf][0] = RNA(p[0]);
                b[nf][1] = RNA(p[4]);
            }
            #pragma unroll
            for (int mf = 0; mf < 4; mf++)
                #pragma unroll
                for (int nf = 0; nf < 4; nf++)
                    mma_tf32(acc[mf][nf], a[mf], b[nf]);
        }
        // no trailing barrier: next iteration's wait+sync protects stage reuse
    }
}

__global__ __launch_bounds__(256, 2) void qkv_mma(const float* __restrict__ X,
                                                  const float* __restrict__ W,
                                                  const float* __restrict__ bias,
                                                  const int* __restrict__ mask) {
    extern __shared__ uint32_t smu[];
    // Fused mask compaction: 4 designated CTAs (exact: softmax is order-
    // invariant; dropped keys would carry weight exp(NEG - max) == 0).
    if (blockIdx.x == 0 && blockIdx.y < BB) {
        const int b = blockIdx.y;
        if (threadIdx.x == 0) g_cnt[b] = 0;
        __syncthreads();
        #pragma unroll
        for (int i = threadIdx.x; i < SSEQ; i += 256) {
            if (mask[b * SSEQ + i] != 0) {
                const int p = atomicAdd(&g_cnt[b], 1);
                g_idx[b * SSEQ + p] = i;
            }
        }
    }

    const int m0 = blockIdx.y << 7, n0 = blockIdx.x << 7;
    float acc[4][4][4] = {};
    mma_mainloop(X + (size_t)m0 * DD, W + (size_t)n0 * DD, smu, acc);

    const int tid = threadIdx.x;
    const int wid = tid >> 5, lane = tid & 31;
    const int wm = wid >> 2, wn = wid & 3;
    const int lr = lane >> 2, lc = lane & 3;

    #pragma unroll
    for (int mf = 0; mf < 4; mf++) {
        #pragma unroll
        for (int nf = 0; nf < 4; nf++) {
            const int cb = n0 + wn*32 + nf*8 + 2*lc;     // even
            const int h   = cb / 192;
            const int rr  = cb - h * 192;
            const int sel = rr >> 6;
            const int dh0 = rr & 63;
            float* gbase = (sel == 0 ? g_q : sel == 1 ? g_k : g_v);
            const float b0 = bias[cb], b1 = bias[cb + 1];
            #pragma unroll
            for (int half = 0; half < 2; half++) {
                const int row = m0 + wm*64 + mf*16 + lr + 8*half;
                const int bI = row >> 11, sI = row & (SSEQ - 1);
                float2 o;
                o.x = acc[mf][nf][2*half + 0] + b0;
                o.y = acc[mf][nf][2*half + 1] + b1;
                *(float2*)(gbase + ((size_t)(bI*HH + h)*SSEQ + sI)*DHH + dh0) = o;
            }
        }
    }
}

__global__ __launch_bounds__(256, 2) void out_mma(const float* __restrict__ W,
                                                  const float* __restrict__ bias,
                                                  float* __restrict__ Out) {
    extern __shared__ uint32_t smu[];
    const int m0 = blockIdx.y << 7, n0 = blockIdx.x << 7;
    float acc[4][4][4] = {};
    mma_mainloop(g_attn + (size_t)m0 * DD, W + (size_t)n0 * DD, smu, acc);

    const int tid = threadIdx.x;
    const int wid = tid >> 5, lane = tid & 31;
    const int wm = wid >> 2, wn = wid & 3;
    const int lr = lane >> 2, lc = lane & 3;

    #pragma unroll
    for (int mf = 0; mf < 4; mf++) {
        #pragma unroll
        for (int nf = 0; nf < 4; nf++) {
            const int cb = n0 + wn*32 + nf*8 + 2*lc;
            const float b0 = bias[cb], b1 = bias[cb + 1];
            #pragma unroll
            for (int half = 0; half < 2; half++) {
                const int row = m0 + wm*64 + mf*16 + lr + 8*half;
                float2 o;
                o.x = acc[mf][nf][2*half + 0] + b0;
                o.y = acc[mf][nf][2*half + 1] + b1;
                *(float2*)(Out + (size_t)row * DD + cb) = o;
            }
        }
    }
}

// ---------------------------------------------------------------------------
// Kernel 2: flash attention, tf32 mma.sync, warp tile 32 q-rows x 64 keys,
// cp.async double-buffered K/V, ONE barrier per tile:
//   wait(t) -> sync -> prefetch(t+1) -> compute(t).
// prefetch(t+1) overwrites buf (t+1)&1, last read by compute(t-1); every
// warp passing sync(t) has finished compute(t-1), so the write is safe and
// the trailing barrier is unnecessary. CTA = 8 warps = 256 q-rows.
// grid: (B*H = 32, S/256 = 8)
// ---------------------------------------------------------------------------
#define QST 68   // Qs/Ps row stride (conflict-free fragment access)
#define KST 68   // Ks row stride [key][dh]
#define VST 72   // Vs row stride [key][dh]; 72%32=8 -> conflict-free B frags

// Full-tile cp.async prefetch: 64 rows x 256 B each for K and V.
__device__ __forceinline__ void prefetch_tile(const float* Kbh, const float* Vbh,
                                              const int* idx, int t, int L,
                                              uint32_t ks_byte, uint32_t vs_byte,
                                              int tid) {
    const uint32_t bo = (uint32_t)((t & 1) * 64);
    #pragma unroll
    for (int it = 0; it < 4; it++) {
        const int i = tid + it * 256;
        const int r = i >> 4;               // key row 0..63
        const int ch = (i & 15) * 16;       // byte chunk within 256B row
        const int rr = (t << 6) + r;
        const int kr = idx[rr < L ? rr : L - 1];
        const void* gk = (const char*)(Kbh + (size_t)kr * DHH) + ch;
        const void* gv = (const char*)(Vbh + (size_t)kr * DHH) + ch;
        const uint32_t dk = ks_byte + (bo + (uint32_t)r) * (KST*4) + ch;
        const uint32_t dv = vs_byte + (bo + (uint32_t)r) * (VST*4) + ch;
        asm volatile("cp.async.cg.shared.global [%0], [%1], 16;" :: "r"(dk), "l"(gk));
        asm volatile("cp.async.cg.shared.global [%0], [%1], 16;" :: "r"(dv), "l"(gv));
    }
    asm volatile("cp.async.commit_group;" ::: "memory");
}

__global__ __launch_bounds__(256) void attn_mma() {
    extern __shared__ uint32_t smu[];
    uint32_t* Qs  = smu;                     // [256][QST] tf32
    uint32_t* Ps  = smu + 256*QST;           // [256][QST] tf32 weights
    uint32_t* KsB = smu + 512*QST;           // [2][64][KST] fp32 (raw)
    uint32_t* VsB = KsB + 2*64*KST;          // [2][64][VST] fp32 (raw)
    const uint32_t sb = smem_u32(smu);
    const uint32_t ks_byte = sb + 512*QST*4;
    const uint32_t vs_byte = ks_byte + 2*64*KST*4;

    const int tid = threadIdx.x;
    const int wid = tid >> 5, lane = tid & 31;
    const int lr = lane >> 2, lc = lane & 3;
    const int bh = blockIdx.x;
    const int bI = bh >> 3, h = bh & 7;
    const int q0 = blockIdx.y << 8;
    const int L  = g_cnt[bI];
    const int* idx = g_idx + bI * SSEQ;
    const float* Kbh = g_k + (size_t)bh * SSEQ * DHH;
    const float* Vbh = g_v + (size_t)bh * SSEQ * DHH;
    const int nT = (L + 63) >> 6;

    prefetch_tile(Kbh, Vbh, idx, 0, L, ks_byte, vs_byte, tid);

    // Load Q tile (256 x 64) as tf32 (overlaps with cp.async flight)
    const float* Qg = g_q + ((size_t)bh * SSEQ + q0) * DHH;
    #pragma unroll
    for (int it = 0; it < 16; it++) {
        const int i = tid + it * 256;
        const int r = i >> 4, c4 = (i & 15) << 2;
        const float4 v = *(const float4*)(Qg + r * DHH + c4);
        uint32_t* p = Qs + r * QST + c4;
        p[0] = f2tf32(v.x); p[1] = f2tf32(v.y);
        p[2] = f2tf32(v.z); p[3] = f2tf32(v.w);
    }

    float o[2][8][4] = {};
    float mrow[2][2], lrow[2][2];
    mrow[0][0] = mrow[0][1] = mrow[1][0] = mrow[1][1] = -3.0e38f;
    lrow[0][0] = lrow[0][1] = lrow[1][0] = lrow[1][1] = 0.f;
    const float C = 0.18033688f;   // (1/sqrt(64)) * log2(e)
    const int base = wid << 5;     // warp's first q-row (32 rows per warp)

    for (int t = 0; t < nT; t++) {
        asm volatile("cp.async.wait_group 0;" ::: "memory");   // tile t landed
        __syncthreads();
        if (t + 1 < nT)
            prefetch_tile(Kbh, Vbh, idx, t + 1, L, ks_byte, vs_byte, tid);

        const uint32_t* Kc = KsB + (t & 1) * 64 * KST;
        const uint32_t* Vc = VsB + (t & 1) * 64 * VST;
        const int k0 = t << 6;

        // S = Q K^T  (per warp: 32 rows x 64 keys; B frags shared by 2 blocks)
        float s[2][8][4] = {};
        #pragma unroll
        for (int ks = 0; ks < 8; ks++) {
            uint32_t a[2][4];
            #pragma unroll
            for (int mf = 0; mf < 2; mf++) {
                const uint32_t* pa = Qs + (base + mf*16 + lr) * QST + ks*8 + lc;
                a[mf][0] = pa[0];
                a[mf][1] = pa[8*QST];
                a[mf][2] = pa[4];
                a[mf][3] = pa[8*QST + 4];
            }
            #pragma unroll
            for (int nf = 0; nf < 8; nf++) {
                uint32_t b[2];
                const uint32_t* pb = Kc + (nf*8 + lr) * KST + ks*8 + lc;
                b[0] = pb[0];
                b[1] = pb[4];
                mma_tf32(s[0][nf], a[0], b);
                mma_tf32(s[1][nf], a[1], b);
            }
        }

        // Scale + mask padding columns
        #pragma unroll
        for (int nf = 0; nf < 8; nf++) {
            const int cb = k0 + nf*8 + 2*lc;
            const bool v0 = cb < L, v1 = (cb + 1) < L;
            #pragma unroll
            for (int mf = 0; mf < 2; mf++) {
                s[mf][nf][0] = v0 ? s[mf][nf][0]*C : -3.0e38f;
                s[mf][nf][1] = v1 ? s[mf][nf][1]*C : -3.0e38f;
                s[mf][nf][2] = v0 ? s[mf][nf][2]*C : -3.0e38f;
                s[mf][nf][3] = v1 ? s[mf][nf][3]*C : -3.0e38f;
            }
        }

        // Online softmax per row block
        #pragma unroll
        for (int mf = 0; mf < 2; mf++) {
            float pm0 = -3.0e38f, pm1 = -3.0e38f;
            #pragma unroll
            for (int nf = 0; nf < 8; nf++) {
                pm0 = fmaxf(pm0, fmaxf(s[mf][nf][0], s[mf][nf][1]));
                pm1 = fmaxf(pm1, fmaxf(s[mf][nf][2], s[mf][nf][3]));
            }
            pm0 = fmaxf(pm0, __shfl_xor_sync(0xffffffffu, pm0, 1));
            pm0 = fmaxf(pm0, __shfl_xor_sync(0xffffffffu, pm0, 2));
            pm1 = fmaxf(pm1, __shfl_xor_sync(0xffffffffu, pm1, 1));
            pm1 = fmaxf(pm1, __shfl_xor_sync(0xffffffffu, pm1, 2));

            const float mn0 = fmaxf(mrow[mf][0], pm0);
            const float mn1 = fmaxf(mrow[mf][1], pm1);
            const float al0 = fexp2(mrow[mf][0] - mn0);
            const float al1 = fexp2(mrow[mf][1] - mn1);
            mrow[mf][0] = mn0; mrow[mf][1] = mn1;

            float sum0 = 0.f, sum1 = 0.f;
            uint32_t* Pw0 = Ps + (base + mf*16 + lr) * QST + 2*lc;
            uint32_t* Pw1 = Pw0 + 8*QST;
            #pragma unroll
            for (int nf = 0; nf < 8; nf++) {
                const float p0 = fexp2(s[mf][nf][0] - mn0);
                const float p1 = fexp2(s[mf][nf][1] - mn0);
                const float p2 = fexp2(s[mf][nf][2] - mn1);
                const float p3 = fexp2(s[mf][nf][3] - mn1);
                sum0 += p0 + p1;
                sum1 += p2 + p3;
                Pw0[nf*8 + 0] = f2tf32(p0);
                Pw0[nf*8 + 1] = f2tf32(p1);
                Pw1[nf*8 + 0] = f2tf32(p2);
                Pw1[nf*8 + 1] = f2tf32(p3);
            }
            sum0 += __shfl_xor_sync(0xffffffffu, sum0, 1);
            sum0 += __shfl_xor_sync(0xffffffffu, sum0, 2);
            sum1 += __shfl_xor_sync(0xffffffffu, sum1, 1);
            sum1 += __shfl_xor_sync(0xffffffffu, sum1, 2);
            lrow[mf][0] = lrow[mf][0] * al0 + sum0;
            lrow[mf][1] = lrow[mf][1] * al1 + sum1;

            #pragma unroll
            for (int nf = 0; nf < 8; nf++) {
                o[mf][nf][0] *= al0; o[mf][nf][1] *= al0;
                o[mf][nf][2] *= al1; o[mf][nf][3] *= al1;
            }
        }
        __syncwarp();   // P written by this warp, read by this warp's lanes

        // O += P V   (B frags from Vc[key][dh], shared by 2 row blocks)
        #pragma unroll
        for (int ks = 0; ks < 8; ks++) {
            uint32_t a[2][4];
            #pragma unroll
            for (int mf = 0; mf < 2; mf++) {
                const uint32_t* pa = Ps + (base + mf*16 + lr) * QST + ks*8 + lc;
                a[mf][0] = pa[0];
                a[mf][1] = pa[8*QST];
                a[mf][2] = pa[4];
                a[mf][3] = pa[8*QST + 4];
            }
            #pragma unroll
            for (int nf = 0; nf < 8; nf++) {
                uint32_t b[2];
                const uint32_t* pb = Vc + (ks*8 + lc) * VST + nf*8 + lr;
                b[0] = pb[0];
                b[1] = pb[4*VST];
                mma_tf32(o[0][nf], a[0], b);
                mma_tf32(o[1][nf], a[1], b);
            }
        }
        // no trailing barrier: next iteration's wait+sync protects buffer reuse
    }

    // Epilogue: normalize and write [b,s,d]
    #pragma unroll
    for (int mf = 0; mf < 2; mf++) {
        const float inv0 = 1.f / lrow[mf][0], inv1 = 1.f / lrow[mf][1];
        const int s0 = q0 + base + mf*16 + lr, s1 = s0 + 8;
        float* d0 = g_attn + ((size_t)bI * SSEQ + s0) * DD + h * DHH + 2*lc;
        float* d1 = g_attn + ((size_t)bI * SSEQ + s1) * DD + h * DHH + 2*lc;
        #pragma unroll
        for (int nf = 0; nf < 8; nf++) {
            float2 w0, w1;
            w0.x = o[mf][nf][0] * inv0; w0.y = o[mf][nf][1] * inv0;
            w1.x = o[mf][nf][2] * inv1; w1.y = o[mf][nf][3] * inv1;
            *(float2*)(d0 + nf*8) = w0;
            *(float2*)(d1 + nf*8) = w1;
        }
    }
}

// ---------------------------------------------------------------------------
extern "C" void kernel_launch(void* const* d_in, const int* in_sizes, int n_in,
                              void* d_out, int out_size) {
    const float* x    = (const float*)d_in[0];
    const int*   mask = (const int*)  d_in[1];
    const float* Wqkv = (const float*)d_in[2];
    const float* bqkv = (const float*)d_in[3];
    const float* Wo   = (const float*)d_in[4];
    const float* bo   = (const float*)d_in[5];
    float* out = (float*)d_out;

    const int attn_smem = (512*QST + 2*64*KST + 2*64*VST) * (int)sizeof(uint32_t);
    cudaFuncSetAttribute(attn_mma, cudaFuncAttributeMaxDynamicSharedMemorySize,
                         attn_smem);
    cudaFuncSetAttribute(qkv_mma, cudaFuncAttributeMaxDynamicSharedMemorySize,
                         GEMM_SMEM_BYTES);
    cudaFuncSetAttribute(out_mma, cudaFuncAttributeMaxDynamicSharedMemorySize,
                         GEMM_SMEM_BYTES);

    qkv_mma<<<dim3(E3/128, (BB*SSEQ)/128), 256, GEMM_SMEM_BYTES>>>(x, Wqkv, bqkv, mask);
    attn_mma<<<dim3(BB*HH, SSEQ/256), 256, attn_smem>>>();
    out_mma<<<dim3(DD/128, (BB*SSEQ)/128), 256, GEMM_SMEM_BYTES>>>(Wo, bo, out);
}

// round 14
// speedup vs baseline: 1.5122x; 1.5122x over previous
#include <cuda_runtime.h>
#include <math.h>
#include <stdint.h>

#define BB   4
#define SSEQ 2048
#define DD   512
#define HH   8
#define DHH  64
#define E3   1536

// Scratch (allocation-free rule: __device__ globals)
__device__ float g_q[BB*HH*SSEQ*DHH];    // [b,h,s,dh]
__device__ float g_k[BB*HH*SSEQ*DHH];
__device__ float g_v[BB*HH*SSEQ*DHH];
__device__ float g_attn[BB*SSEQ*DD];     // [b,s,d]
__device__ int   g_cnt[BB];              // active-key count per batch
__device__ int   g_idx[BB*SSEQ];         // active key indices (unordered)

// ---------------------------------------------------------------------------
// TF32 mma.sync helpers (plain sm_80+ PTX)
// ---------------------------------------------------------------------------
__device__ __forceinline__ uint32_t f2tf32(float x) {
    uint32_t y;
    asm("cvt.rna.tf32.f32 %0, %1;" : "=r"(y) : "f"(x));
    return y;
}
// Register-time round-to-nearest for raw fp32 bits fed to tf32 MMA.
#define RNA(x) ((x) + 0x1000u)

__device__ __forceinline__ void mma_tf32(float (&d)[4], const uint32_t (&a)[4],
                                         const uint32_t (&b)[2]) {
    asm volatile("mma.sync.aligned.m16n8k8.row.col.f32.tf32.tf32.f32 "
                 "{%0,%1,%2,%3}, {%4,%5,%6,%7}, {%8,%9}, {%0,%1,%2,%3};"
                 : "+f"(d[0]), "+f"(d[1]), "+f"(d[2]), "+f"(d[3])
                 : "r"(a[0]), "r"(a[1]), "r"(a[2]), "r"(a[3]),
                   "r"(b[0]), "r"(b[1]));
}
__device__ __forceinline__ uint32_t smem_u32(const void* p) {
    uint32_t a;
    asm("{ .reg .u64 t; cvta.to.shared.u64 t, %1; cvt.u32.u64 %0, t; }"
        : "=r"(a) : "l"(p));
    return a;
}

// Fast 2^x for x <= 0 on the FMA pipe (no MUFU). Rel err ~4e-5.
__device__ __forceinline__ float fexp2(float x) {
    x = fmaxf(x, -126.0f);
    const float z = x + 12582912.0f;                       // 1.5*2^23
    const int   n = (__float_as_int(z) & 0x7FFFFF) - 0x400000;
    const float f = x - (z - 12582912.0f);
    float p = fmaf(fmaf(fmaf(fmaf(0.00961813f, f, 0.05550411f),
                             f, 0.24022651f), f, 0.69314718f), f, 1.0f);
    return __int_as_float(__float_as_int(p) + (n << 23));
}

// ---------------------------------------------------------------------------
// Projection GEMMs: 128x128 CTA tile, 8 warps (2M x 4N), warp tile 64x32.
// cp.async 3-stage pipeline with ONE barrier per chunk:
//   wait(ch) -> sync -> prefetch(ch+2) -> compute(ch).
// Stage ch%3 is only rewritten by prefetch(ch+3), which every warp issues
// after the NEXT barrier, i.e. after all warps finished compute(ch).
// ---------------------------------------------------------------------------
#define GST 36
#define KC  32
#define NCH (DD/KC)          // 16 chunks
#define NST 3                // pipeline stages
#define GEMM_TILE_U32 (128*GST)
#define GEMM_SMEM_BYTES (NST * 2 * GEMM_TILE_U32 * 4)   // 110592

__device__ __forceinline__ void gemm_prefetch(const float* __restrict__ Ag,
                                              const float* __restrict__ Bg,
                                              int ch, uint32_t a_byte,
                                              uint32_t b_byte, int tid) {
    const uint32_t so = (uint32_t)((ch % NST) * 2 * GEMM_TILE_U32 * 4);
    #pragma unroll
    for (int it = 0; it < 4; it++) {
        const int i = tid + it * 256;
        const int r = i >> 3;               // row 0..127
        const int c = (i & 7) * 16;         // byte chunk within 128B row
        const void* ga = (const char*)(Ag + (size_t)r * DD + ch * KC) + c;
        const void* gb = (const char*)(Bg + (size_t)r * DD + ch * KC) + c;
        const uint32_t da = a_byte + so + (uint32_t)r * (GST*4) + c;
        const uint32_t db = b_byte + so + (uint32_t)r * (GST*4) + c;
        asm volatile("cp.async.cg.shared.global [%0], [%1], 16;" :: "r"(da), "l"(ga));
        asm volatile("cp.async.cg.shared.global [%0], [%1], 16;" :: "r"(db), "l"(gb));
    }
    asm volatile("cp.async.commit_group;" ::: "memory");
}

__device__ __forceinline__ void mma_mainloop(const float* __restrict__ Ag,
                                             const float* __restrict__ Bg,
                                             uint32_t* smu,
                                             float acc[4][4][4]) {
    const int tid = threadIdx.x;
    const int wid = tid >> 5, lane = tid & 31;
    const int wm = wid >> 2, wn = wid & 3;
    const int lr = lane >> 2, lc = lane & 3;
    const uint32_t sb = smem_u32(smu);
    const uint32_t a_byte = sb;
    const uint32_t b_byte = sb + GEMM_TILE_U32 * 4;

    gemm_prefetch(Ag, Bg, 0, a_byte, b_byte, tid);
    gemm_prefetch(Ag, Bg, 1, a_byte, b_byte, tid);

    for (int ch = 0; ch < NCH; ch++) {
        asm volatile("cp.async.wait_group 1;" ::: "memory");   // chunk ch landed
        __syncthreads();
        if (ch + 2 < NCH)
            gemm_prefetch(Ag, Bg, ch + 2, a_byte, b_byte, tid);
        else
            asm volatile("cp.async.commit_group;" ::: "memory");  // empty group

        const uint32_t* As = smu + (ch % NST) * 2 * GEMM_TILE_U32;
        const uint32_t* Bs = As + GEMM_TILE_U32;

        #pragma unroll
        for (int ks = 0; ks < KC; ks += 8) {
            uint32_t a[4][4], b[4][2];
            #pragma unroll
            for (int mf = 0; mf < 4; mf++) {
                const uint32_t* p = As + (wm*64 + mf*16 + lr) * GST + ks + lc;
                a[mf][0] = RNA(p[0]);
                a[mf][1] = RNA(p[8*GST]);
                a[mf][2] = RNA(p[4]);
                a[mf][3] = RNA(p[8*GST + 4]);
            }
            #pragma unroll
            for (int nf = 0; nf < 4; nf++) {
                const uint32_t* p = Bs + (wn*32 + nf*8 + lr) * GST + ks + lc;
                b[nf][0] = RNA(p[0]);
                b[nf][1] = RNA(p[4]);
            }
            #pragma unroll
            for (int mf = 0; mf < 4; mf++)
                #pragma unroll
                for (int nf = 0; nf < 4; nf++)
                    mma_tf32(acc[mf][nf], a[mf], b[nf]);
        }
        // no trailing barrier: next iteration's wait+sync protects stage reuse
    }
}

__global__ __launch_bounds__(256, 2) void qkv_mma(const float* __restrict__ X,
                                                  const float* __restrict__ W,
                                                  const float* __restrict__ bias,
                                                  const int* __restrict__ mask) {
    extern __shared__ uint32_t smu[];
    // Fused mask compaction: 4 designated CTAs (exact: softmax is order-
    // invariant; dropped keys would carry weight exp(NEG - max) == 0).
    if (blockIdx.x == 0 && blockIdx.y < BB) {
        const int b = blockIdx.y;
        if (threadIdx.x == 0) g_cnt[b] = 0;
        __syncthreads();
        #pragma unroll
        for (int i = threadIdx.x; i < SSEQ; i += 256) {
            if (mask[b * SSEQ + i] != 0) {
                const int p = atomicAdd(&g_cnt[b], 1);
                g_idx[b * SSEQ + p] = i;
            }
        }
    }

    const int m0 = blockIdx.y << 7, n0 = blockIdx.x << 7;
    float acc[4][4][4] = {};
    mma_mainloop(X + (size_t)m0 * DD, W + (size_t)n0 * DD, smu, acc);

    const int tid = threadIdx.x;
    const int wid = tid >> 5, lane = tid & 31;
    const int wm = wid >> 2, wn = wid & 3;
    const int lr = lane >> 2, lc = lane & 3;

    #pragma unroll
    for (int mf = 0; mf < 4; mf++) {
        #pragma unroll
        for (int nf = 0; nf < 4; nf++) {
            const int cb = n0 + wn*32 + nf*8 + 2*lc;     // even
            const int h   = cb / 192;
            const int rr  = cb - h * 192;
            const int sel = rr >> 6;
            const int dh0 = rr & 63;
            float* gbase = (sel == 0 ? g_q : sel == 1 ? g_k : g_v);
            const float b0 = bias[cb], b1 = bias[cb + 1];
            #pragma unroll
            for (int half = 0; half < 2; half++) {
                const int row = m0 + wm*64 + mf*16 + lr + 8*half;
                const int bI = row >> 11, sI = row & (SSEQ - 1);
                float2 o;
                o.x = acc[mf][nf][2*half + 0] + b0;
                o.y = acc[mf][nf][2*half + 1] + b1;
                *(float2*)(gbase + ((size_t)(bI*HH + h)*SSEQ + sI)*DHH + dh0) = o;
            }
        }
    }
}

__global__ __launch_bounds__(256, 2) void out_mma(const float* __restrict__ W,
                                                  const float* __restrict__ bias,
                                                  float* __restrict__ Out) {
    extern __shared__ uint32_t smu[];
    const int m0 = blockIdx.y << 7, n0 = blockIdx.x << 7;
    float acc[4][4][4] = {};
    mma_mainloop(g_attn + (size_t)m0 * DD, W + (size_t)n0 * DD, smu, acc);

    const int tid = threadIdx.x;
    const int wid = tid >> 5, lane = tid & 31;
    const int wm = wid >> 2, wn = wid & 3;
    const int lr = lane >> 2, lc = lane & 3;

    #pragma unroll
    for (int mf = 0; mf < 4; mf++) {
        #pragma unroll
        for (int nf = 0; nf < 4; nf++) {
            const int cb = n0 + wn*32 + nf*8 + 2*lc;
            const float b0 = bias[cb], b1 = bias[cb + 1];
            #pragma unroll
            for (int half = 0; half < 2; half++) {
                const int row = m0 + wm*64 + mf*16 + lr + 8*half;
                float2 o;
                o.x = acc[mf][nf][2*half + 0] + b0;
                o.y = acc[mf][nf][2*half + 1] + b1;
                *(float2*)(Out + (size_t)row * DD + cb) = o;
            }
        }
    }
}

// ---------------------------------------------------------------------------
// Kernel 2: flash attention, tf32 mma.sync, warp tile 32 q-rows x 64 keys,
// cp.async double-buffered K/V pipeline. CTA = 8 warps = 256 q-rows.
// grid: (B*H = 32, S/256 = 8)    [round-10/12 proven version]
// ---------------------------------------------------------------------------
#define QST 68   // Qs/Ps row stride (conflict-free fragment access)
#define KST 68   // Ks row stride [key][dh]
#define VST 72   // Vs row stride [key][dh]; 72%32=8 -> conflict-free B frags

// Full-tile cp.async prefetch: 64 rows x 256 B each for K and V.
__device__ __forceinline__ void prefetch_tile(const float* Kbh, const float* Vbh,
                                              const int* idx, int t, int L,
                                              uint32_t ks_byte, uint32_t vs_byte,
                                              int tid) {
    const uint32_t bo = (uint32_t)((t & 1) * 64);
    #pragma unroll
    for (int it = 0; it < 4; it++) {
        const int i = tid + it * 256;
        const int r = i >> 4;               // key row 0..63
        const int ch = (i & 15) * 16;       // byte chunk within 256B row
        const int rr = (t << 6) + r;
        const int kr = idx[rr < L ? rr : L - 1];
        const void* gk = (const char*)(Kbh + (size_t)kr * DHH) + ch;
        const void* gv = (const char*)(Vbh + (size_t)kr * DHH) + ch;
        const uint32_t dk = ks_byte + (bo + (uint32_t)r) * (KST*4) + ch;
        const uint32_t dv = vs_byte + (bo + (uint32_t)r) * (VST*4) + ch;
        asm volatile("cp.async.cg.shared.global [%0], [%1], 16;" :: "r"(dk), "l"(gk));
        asm volatile("cp.async.cg.shared.global [%0], [%1], 16;" :: "r"(dv), "l"(gv));
    }
    asm volatile("cp.async.commit_group;" ::: "memory");
}

__global__ __launch_bounds__(256) void attn_mma() {
    extern __shared__ uint32_t smu[];
    uint32_t* Qs  = smu;                     // [256][QST] tf32
    uint32_t* Ps  = smu + 256*QST;           // [256][QST] tf32 weights
    uint32_t* KsB = smu + 512*QST;           // [2][64][KST] fp32 (raw)
    uint32_t* VsB = KsB + 2*64*KST;          // [2][64][VST] fp32 (raw)
    const uint32_t sb = smem_u32(smu);
    const uint32_t ks_byte = sb + 512*QST*4;
    const uint32_t vs_byte = ks_byte + 2*64*KST*4;

    const int tid = threadIdx.x;
    const int wid = tid >> 5, lane = tid & 31;
    const int lr = lane >> 2, lc = lane & 3;
    const int bh = blockIdx.x;
    const int bI = bh >> 3, h = bh & 7;
    const int q0 = blockIdx.y << 8;
    const int L  = g_cnt[bI];
    const int* idx = g_idx + bI * SSEQ;
    const float* Kbh = g_k + (size_t)bh * SSEQ * DHH;
    const float* Vbh = g_v + (size_t)bh * SSEQ * DHH;
    const int nT = (L + 63) >> 6;

    prefetch_tile(Kbh, Vbh, idx, 0, L, ks_byte, vs_byte, tid);

    // Load Q tile (256 x 64) as tf32 (overlaps with cp.async flight)
    const float* Qg = g_q + ((size_t)bh * SSEQ + q0) * DHH;
    #pragma unroll
    for (int it = 0; it < 16; it++) {
        const int i = tid + it * 256;
        const int r = i >> 4, c4 = (i & 15) << 2;
        const float4 v = *(const float4*)(Qg + r * DHH + c4);
        uint32_t* p = Qs + r * QST + c4;
        p[0] = f2tf32(v.x); p[1] = f2tf32(v.y);
        p[2] = f2tf32(v.z); p[3] = f2tf32(v.w);
    }

    float o[2][8][4] = {};
    float mrow[2][2], lrow[2][2];
    mrow[0][0] = mrow[0][1] = mrow[1][0] = mrow[1][1] = -3.0e38f;
    lrow[0][0] = lrow[0][1] = lrow[1][0] = lrow[1][1] = 0.f;
    const float C = 0.18033688f;   // (1/sqrt(64)) * log2(e)
    const int base = wid << 5;     // warp's first q-row (32 rows per warp)

    for (int t = 0; t < nT; t++) {
        prefetch_tile(Kbh, Vbh, idx, (t + 1 < nT) ? t + 1 : nT - 1, L,
                      ks_byte, vs_byte, tid);
        asm volatile("cp.async.wait_group 1;" ::: "memory");   // tile t landed
        __syncthreads();

        const uint32_t* Kc = KsB + (t & 1) * 64 * KST;
        const uint32_t* Vc = VsB + (t & 1) * 64 * VST;
        const int k0 = t << 6;

        // S = Q K^T  (per warp: 32 rows x 64 keys; B frags shared by 2 blocks)
        float s[2][8][4] = {};
        #pragma unroll
        for (int ks = 0; ks < 8; ks++) {
            uint32_t a[2][4];
            #pragma unroll
            for (int mf = 0; mf < 2; mf++) {
                const uint32_t* pa = Qs + (base + mf*16 + lr) * QST + ks*8 + lc;
                a[mf][0] = pa[0];
                a[mf][1] = pa[8*QST];
                a[mf][2] = pa[4];
                a[mf][3] = pa[8*QST + 4];
            }
            #pragma unroll
            for (int nf = 0; nf < 8; nf++) {
                uint32_t b[2];
                const uint32_t* pb = Kc + (nf*8 + lr) * KST + ks*8 + lc;
                b[0] = pb[0];
                b[1] = pb[4];
                mma_tf32(s[0][nf], a[0], b);
                mma_tf32(s[1][nf], a[1], b);
            }
        }

        // Scale + mask padding columns
        #pragma unroll
        for (int nf = 0; nf < 8; nf++) {
            const int cb = k0 + nf*8 + 2*lc;
            const bool v0 = cb < L, v1 = (cb + 1) < L;
            #pragma unroll
            for (int mf = 0; mf < 2; mf++) {
                s[mf][nf][0] = v0 ? s[mf][nf][0]*C : -3.0e38f;
                s[mf][nf][1] = v1 ? s[mf][nf][1]*C : -3.0e38f;
                s[mf][nf][2] = v0 ? s[mf][nf][2]*C : -3.0e38f;
                s[mf][nf][3] = v1 ? s[mf][nf][3]*C : -3.0e38f;
            }
        }

        // Online softmax per row block
        #pragma unroll
        for (int mf = 0; mf < 2; mf++) {
            float pm0 = -3.0e38f, pm1 = -3.0e38f;
            #pragma unroll
            for (int nf = 0; nf < 8; nf++) {
                pm0 = fmaxf(pm0, fmaxf(s[mf][nf][0], s[mf][nf][1]));
                pm1 = fmaxf(pm1, fmaxf(s[mf][nf][2], s[mf][nf][3]));
            }
            pm0 = fmaxf(pm0, __shfl_xor_sync(0xffffffffu, pm0, 1));
            pm0 = fmaxf(pm0, __shfl_xor_sync(0xffffffffu, pm0, 2));
            pm1 = fmaxf(pm1, __shfl_xor_sync(0xffffffffu, pm1, 1));
            pm1 = fmaxf(pm1, __shfl_xor_sync(0xffffffffu, pm1, 2));

            const float mn0 = fmaxf(mrow[mf][0], pm0);
            const float mn1 = fmaxf(mrow[mf][1], pm1);
            const float al0 = fexp2(mrow[mf][0] - mn0);
            const float al1 = fexp2(mrow[mf][1] - mn1);
            mrow[mf][0] = mn0; mrow[mf][1] = mn1;

            float sum0 = 0.f, sum1 = 0.f;
            uint32_t* Pw0 = Ps + (base + mf*16 + lr) * QST + 2*lc;
            uint32_t* Pw1 = Pw0 + 8*QST;
            #pragma unroll
            for (int nf = 0; nf < 8; nf++) {
                const float p0 = fexp2(s[mf][nf][0] - mn0);
                const float p1 = fexp2(s[mf][nf][1] - mn0);
                const float p2 = fexp2(s[mf][nf][2] - mn1);
                const float p3 = fexp2(s[mf][nf][3] - mn1);
                sum0 += p0 + p1;
                sum1 += p2 + p3;
                Pw0[nf*8 + 0] = f2tf32(p0);
                Pw0[nf*8 + 1] = f2tf32(p1);
                Pw1[nf*8 + 0] = f2tf32(p2);
                Pw1[nf*8 + 1] = f2tf32(p3);
            }
            sum0 += __shfl_xor_sync(0xffffffffu, sum0, 1);
            sum0 += __shfl_xor_sync(0xffffffffu, sum0, 2);
            sum1 += __shfl_xor_sync(0xffffffffu, sum1, 1);
            sum1 += __shfl_xor_sync(0xffffffffu, sum1, 2);
            lrow[mf][0] = lrow[mf][0] * al0 + sum0;
            lrow[mf][1] = lrow[mf][1] * al1 + sum1;

            #pragma unroll
            for (int nf = 0; nf < 8; nf++) {
                o[mf][nf][0] *= al0; o[mf][nf][1] *= al0;
                o[mf][nf][2] *= al1; o[mf][nf][3] *= al1;
            }
        }
        __syncwarp();   // P written by this warp, read by this warp's lanes

        // O += P V   (B frags from Vc[key][dh], shared by 2 row blocks)
        #pragma unroll
        for (int ks = 0; ks < 8; ks++) {
            uint32_t a[2][4];
            #pragma unroll
            for (int mf = 0; mf < 2; mf++) {
                const uint32_t* pa = Ps + (base + mf*16 + lr) * QST + ks*8 + lc;
                a[mf][0] = pa[0];
                a[mf][1] = pa[8*QST];
                a[mf][2] = pa[4];
                a[mf][3] = pa[8*QST + 4];
            }
            #pragma unroll
            for (int nf = 0; nf < 8; nf++) {
                uint32_t b[2];
                const uint32_t* pb = Vc + (ks*8 + lc) * VST + nf*8 + lr;
                b[0] = pb[0];
                b[1] = pb[4*VST];
                mma_tf32(o[0][nf], a[0], b);
                mma_tf32(o[1][nf], a[1], b);
            }
        }
        __syncthreads();   // all reads of buf t&1 done before t+1 prefetch hits it
    }

    // Epilogue: normalize and write [b,s,d]
    #pragma unroll
    for (int mf = 0; mf < 2; mf++) {
        const float inv0 = 1.f / lrow[mf][0], inv1 = 1.f / lrow[mf][1];
        const int s0 = q0 + base + mf*16 + lr, s1 = s0 + 8;
        float* d0 = g_attn + ((size_t)bI * SSEQ + s0) * DD + h * DHH + 2*lc;
        float* d1 = g_attn + ((size_t)bI * SSEQ + s1) * DD + h * DHH + 2*lc;
        #pragma unroll
        for (int nf = 0; nf < 8; nf++) {
            float2 w0, w1;
            w0.x = o[mf][nf][0] * inv0; w0.y = o[mf][nf][1] * inv0;
            w1.x = o[mf][nf][2] * inv1; w1.y = o[mf][nf][3] * inv1;
            *(float2*)(d0 + nf*8) = w0;
            *(float2*)(d1 + nf*8) = w1;
        }
    }
}

// ---------------------------------------------------------------------------
extern "C" void kernel_launch(void* const* d_in, const int* in_sizes, int n_in,
                              void* d_out, int out_size) {
    const float* x    = (const float*)d_in[0];
    const int*   mask = (const int*)  d_in[1];
    const float* Wqkv = (const float*)d_in[2];
    const float* bqkv = (const float*)d_in[3];
    const float* Wo   = (const float*)d_in[4];
    const float* bo   = (const float*)d_in[5];
    float* out = (float*)d_out;

    const int attn_smem = (512*QST + 2*64*KST + 2*64*VST) * (int)sizeof(uint32_t);
    cudaFuncSetAttribute(attn_mma, cudaFuncAttributeMaxDynamicSharedMemorySize,
                         attn_smem);
    cudaFuncSetAttribute(qkv_mma, cudaFuncAttributeMaxDynamicSharedMemorySize,
                         GEMM_SMEM_BYTES);
    cudaFuncSetAttribute(out_mma, cudaFuncAttributeMaxDynamicSharedMemorySize,
                         GEMM_SMEM_BYTES);

    qkv_mma<<<dim3(E3/128, (BB*SSEQ)/128), 256, GEMM_SMEM_BYTES>>>(x, Wqkv, bqkv, mask);
    attn_mma<<<dim3(BB*HH, SSEQ/256), 256, attn_smem>>>();
    out_mma<<<dim3(DD/128, (BB*SSEQ)/128), 256, GEMM_SMEM_BYTES>>>(Wo, bo, out);
}

// round 15
// speedup vs baseline: 1.5447x; 1.0215x over previous
#include <cuda_runtime.h>
#include <math.h>
#include <stdint.h>

#define BB   4
#define SSEQ 2048
#define DD   512
#define HH   8
#define DHH  64
#define E3   1536

// Scratch (allocation-free rule: __device__ globals)
__device__ float g_q[BB*HH*SSEQ*DHH];    // [b,h,s,dh]
__device__ float g_k[BB*HH*SSEQ*DHH];
__device__ float g_v[BB*HH*SSEQ*DHH];
__device__ float g_attn[BB*SSEQ*DD];     // [b,s,d]
__device__ int   g_cnt[BB];              // active-key count per batch
__device__ int   g_idx[BB*SSEQ];         // active key indices (unordered)

// ---------------------------------------------------------------------------
// TF32 mma.sync helpers (plain sm_80+ PTX)
// ---------------------------------------------------------------------------
__device__ __forceinline__ uint32_t f2tf32(float x) {
    uint32_t y;
    asm("cvt.rna.tf32.f32 %0, %1;" : "=r"(y) : "f"(x));
    return y;
}
// Register-time round-to-nearest for raw fp32 bits fed to tf32 MMA.
#define RNA(x) ((x) + 0x1000u)

__device__ __forceinline__ void mma_tf32(float (&d)[4], const uint32_t (&a)[4],
                                         const uint32_t (&b)[2]) {
    asm volatile("mma.sync.aligned.m16n8k8.row.col.f32.tf32.tf32.f32 "
                 "{%0,%1,%2,%3}, {%4,%5,%6,%7}, {%8,%9}, {%0,%1,%2,%3};"
                 : "+f"(d[0]), "+f"(d[1]), "+f"(d[2]), "+f"(d[3])
                 : "r"(a[0]), "r"(a[1]), "r"(a[2]), "r"(a[3]),
                   "r"(b[0]), "r"(b[1]));
}
__device__ __forceinline__ uint32_t smem_u32(const void* p) {
    uint32_t a;
    asm("{ .reg .u64 t; cvta.to.shared.u64 t, %1; cvt.u32.u64 %0, t; }"
        : "=r"(a) : "l"(p));
    return a;
}

// Fast 2^x for x <= 0 on the FMA pipe (no MUFU). Rel err ~4e-5.
__device__ __forceinline__ float fexp2(float x) {
    x = fmaxf(x, -126.0f);
    const float z = x + 12582912.0f;                       // 1.5*2^23
    const int   n = (__float_as_int(z) & 0x7FFFFF) - 0x400000;
    const float f = x - (z - 12582912.0f);
    float p = fmaf(fmaf(fmaf(fmaf(0.00961813f, f, 0.05550411f),
                             f, 0.24022651f), f, 0.69314718f), f, 1.0f);
    return __int_as_float(__float_as_int(p) + (n << 23));
}

// ---------------------------------------------------------------------------
// Projection GEMMs: 128x128 CTA tile, 8 warps (2M x 4N), warp tile 64x32.
// cp.async 3-stage pipeline with ONE barrier per chunk:
//   wait(ch) -> sync -> prefetch(ch+2) -> compute(ch).
// ---------------------------------------------------------------------------
#define GST 36
#define KC  32
#define NCH (DD/KC)          // 16 chunks
#define NST 3                // pipeline stages
#define GEMM_TILE_U32 (128*GST)
#define GEMM_SMEM_BYTES (NST * 2 * GEMM_TILE_U32 * 4)   // 110592

__device__ __forceinline__ void gemm_prefetch(const float* __restrict__ Ag,
                                              const float* __restrict__ Bg,
                                              int ch, uint32_t a_byte,
                                              uint32_t b_byte, int tid) {
    const uint32_t so = (uint32_t)((ch % NST) * 2 * GEMM_TILE_U32 * 4);
    #pragma unroll
    for (int it = 0; it < 4; it++) {
        const int i = tid + it * 256;
        const int r = i >> 3;               // row 0..127
        const int c = (i & 7) * 16;         // byte chunk within 128B row
        const void* ga = (const char*)(Ag + (size_t)r * DD + ch * KC) + c;
        const void* gb = (const char*)(Bg + (size_t)r * DD + ch * KC) + c;
        const uint32_t da = a_byte + so + (uint32_t)r * (GST*4) + c;
        const uint32_t db = b_byte + so + (uint32_t)r * (GST*4) + c;
        asm volatile("cp.async.cg.shared.global [%0], [%1], 16;" :: "r"(da), "l"(ga));
        asm volatile("cp.async.cg.shared.global [%0], [%1], 16;" :: "r"(db), "l"(gb));
    }
    asm volatile("cp.async.commit_group;" ::: "memory");
}

__device__ __forceinline__ void mma_mainloop(const float* __restrict__ Ag,
                                             const float* __restrict__ Bg,
                                             uint32_t* smu,
                                             float acc[4][4][4]) {
    const int tid = threadIdx.x;
    const int wid = tid >> 5, lane = tid & 31;
    const int wm = wid >> 2, wn = wid & 3;
    const int lr = lane >> 2, lc = lane & 3;
    const uint32_t sb = smem_u32(smu);
    const uint32_t a_byte = sb;
    const uint32_t b_byte = sb + GEMM_TILE_U32 * 4;

    gemm_prefetch(Ag, Bg, 0, a_byte, b_byte, tid);
    gemm_prefetch(Ag, Bg, 1, a_byte, b_byte, tid);

    for (int ch = 0; ch < NCH; ch++) {
        asm volatile("cp.async.wait_group 1;" ::: "memory");   // chunk ch landed
        __syncthreads();
        if (ch + 2 < NCH)
            gemm_prefetch(Ag, Bg, ch + 2, a_byte, b_byte, tid);
        else
            asm volatile("cp.async.commit_group;" ::: "memory");  // empty group

        const uint32_t* As = smu + (ch % NST) * 2 * GEMM_TILE_U32;
        const uint32_t* Bs = As + GEMM_TILE_U32;

        #pragma unroll
        for (int ks = 0; ks < KC; ks += 8) {
            uint32_t a[4][4], b[4][2];
            #pragma unroll
            for (int mf = 0; mf < 4; mf++) {
                const uint32_t* p = As + (wm*64 + mf*16 + lr) * GST + ks + lc;
                a[mf][0] = RNA(p[0]);
                a[mf][1] = RNA(p[8*GST]);
                a[mf][2] = RNA(p[4]);
                a[mf][3] = RNA(p[8*GST + 4]);
            }
            #pragma unroll
            for (int nf = 0; nf < 4; nf++) {
                const uint32_t* p = Bs + (wn*32 + nf*8 + lr) * GST + ks + lc;
                b[nf][0] = RNA(p[0]);
                b[nf][1] = RNA(p[4]);
            }
            #pragma unroll
            for (int mf = 0; mf < 4; mf++)
                #pragma unroll
                for (int nf = 0; nf < 4; nf++)
                    mma_tf32(acc[mf][nf], a[mf], b[nf]);
        }
        // no trailing barrier: next iteration's wait+sync protects stage reuse
    }
}

__global__ __launch_bounds__(256, 2) void qkv_mma(const float* __restrict__ X,
                                                  const float* __restrict__ W,
                                                  const float* __restrict__ bias,
                                                  const int* __restrict__ mask) {
    extern __shared__ uint32_t smu[];
    // Fused mask compaction: 4 designated CTAs (exact: softmax is order-
    // invariant; dropped keys would carry weight exp(NEG - max) == 0).
    if (blockIdx.x == 0 && blockIdx.y < BB) {
        const int b = blockIdx.y;
        if (threadIdx.x == 0) g_cnt[b] = 0;
        __syncthreads();
        #pragma unroll
        for (int i = threadIdx.x; i < SSEQ; i += 256) {
            if (mask[b * SSEQ + i] != 0) {
                const int p = atomicAdd(&g_cnt[b], 1);
                g_idx[b * SSEQ + p] = i;
            }
        }
    }

    const int m0 = blockIdx.y << 7, n0 = blockIdx.x << 7;
    float acc[4][4][4] = {};
    mma_mainloop(X + (size_t)m0 * DD, W + (size_t)n0 * DD, smu, acc);

    const int tid = threadIdx.x;
    const int wid = tid >> 5, lane = tid & 31;
    const int wm = wid >> 2, wn = wid & 3;
    const int lr = lane >> 2, lc = lane & 3;

    #pragma unroll
    for (int mf = 0; mf < 4; mf++) {
        #pragma unroll
        for (int nf = 0; nf < 4; nf++) {
            const int cb = n0 + wn*32 + nf*8 + 2*lc;     // even
            const int h   = cb / 192;
            const int rr  = cb - h * 192;
            const int sel = rr >> 6;
            const int dh0 = rr & 63;
            float* gbase = (sel == 0 ? g_q : sel == 1 ? g_k : g_v);
            const float b0 = bias[cb], b1 = bias[cb + 1];
            #pragma unroll
            for (int half = 0; half < 2; half++) {
                const int row = m0 + wm*64 + mf*16 + lr + 8*half;
                const int bI = row >> 11, sI = row & (SSEQ - 1);
                float2 o;
                o.x = acc[mf][nf][2*half + 0] + b0;
                o.y = acc[mf][nf][2*half + 1] + b1;
                *(float2*)(gbase + ((size_t)(bI*HH + h)*SSEQ + sI)*DHH + dh0) = o;
            }
        }
    }
}

__global__ __launch_bounds__(256, 2) void out_mma(const float* __restrict__ W,
                                                  const float* __restrict__ bias,
                                                  float* __restrict__ Out) {
    extern __shared__ uint32_t smu[];
    const int m0 = blockIdx.y << 7, n0 = blockIdx.x << 7;
    float acc[4][4][4] = {};
    mma_mainloop(g_attn + (size_t)m0 * DD, W + (size_t)n0 * DD, smu, acc);

    const int tid = threadIdx.x;
    const int wid = tid >> 5, lane = tid & 31;
    const int wm = wid >> 2, wn = wid & 3;
    const int lr = lane >> 2, lc = lane & 3;

    #pragma unroll
    for (int mf = 0; mf < 4; mf++) {
        #pragma unroll
        for (int nf = 0; nf < 4; nf++) {
            const int cb = n0 + wn*32 + nf*8 + 2*lc;
            const float b0 = bias[cb], b1 = bias[cb + 1];
            #pragma unroll
            for (int half = 0; half < 2; half++) {
                const int row = m0 + wm*64 + mf*16 + lr + 8*half;
                float2 o;
                o.x = acc[mf][nf][2*half + 0] + b0;
                o.y = acc[mf][nf][2*half + 1] + b1;
                *(float2*)(Out + (size_t)row * DD + cb) = o;
            }
        }
    }
}

// ---------------------------------------------------------------------------
// Kernel 2: flash attention, tf32 mma.sync, warp tile 32 q-rows x 64 keys,
// cp.async double-buffered K/V, ONE barrier per tile:
//   wait(t) -> sync -> prefetch(t+1) -> compute(t).
// prefetch(t+1) overwrites buf (t+1)&1, last read by compute(t-1); every
// warp passing sync(t) has finished compute(t-1), so the write is safe and
// the trailing barrier is unnecessary. CTA = 8 warps = 256 q-rows.
// grid: (B*H = 32, S/256 = 8)
// ---------------------------------------------------------------------------
#define QST 68   // Qs/Ps row stride (conflict-free fragment access)
#define KST 68   // Ks row stride [key][dh]
#define VST 72   // Vs row stride [key][dh]; 72%32=8 -> conflict-free B frags

// Full-tile cp.async prefetch: 64 rows x 256 B each for K and V.
__device__ __forceinline__ void prefetch_tile(const float* Kbh, const float* Vbh,
                                              const int* idx, int t, int L,
                                              uint32_t ks_byte, uint32_t vs_byte,
                                              int tid) {
    const uint32_t bo = (uint32_t)((t & 1) * 64);
    #pragma unroll
    for (int it = 0; it < 4; it++) {
        const int i = tid + it * 256;
        const int r = i >> 4;               // key row 0..63
        const int ch = (i & 15) * 16;       // byte chunk within 256B row
        const int rr = (t << 6) + r;
        const int kr = idx[rr < L ? rr : L - 1];
        const void* gk = (const char*)(Kbh + (size_t)kr * DHH) + ch;
        const void* gv = (const char*)(Vbh + (size_t)kr * DHH) + ch;
        const uint32_t dk = ks_byte + (bo + (uint32_t)r) * (KST*4) + ch;
        const uint32_t dv = vs_byte + (bo + (uint32_t)r) * (VST*4) + ch;
        asm volatile("cp.async.cg.shared.global [%0], [%1], 16;" :: "r"(dk), "l"(gk));
        asm volatile("cp.async.cg.shared.global [%0], [%1], 16;" :: "r"(dv), "l"(gv));
    }
    asm volatile("cp.async.commit_group;" ::: "memory");
}

__global__ __launch_bounds__(256) void attn_mma() {
    extern __shared__ uint32_t smu[];
    uint32_t* Qs  = smu;                     // [256][QST] tf32
    uint32_t* Ps  = smu + 256*QST;           // [256][QST] tf32 weights
    uint32_t* KsB = smu + 512*QST;           // [2][64][KST] fp32 (raw)
    uint32_t* VsB = KsB + 2*64*KST;          // [2][64][VST] fp32 (raw)
    const uint32_t sb = smem_u32(smu);
    const uint32_t ks_byte = sb + 512*QST*4;
    const uint32_t vs_byte = ks_byte + 2*64*KST*4;

    const int tid = threadIdx.x;
    const int wid = tid >> 5, lane = tid & 31;
    const int lr = lane >> 2, lc = lane & 3;
    const int bh = blockIdx.x;
    const int bI = bh >> 3, h = bh & 7;
    const int q0 = blockIdx.y << 8;
    const int L  = g_cnt[bI];
    const int* idx = g_idx + bI * SSEQ;
    const float* Kbh = g_k + (size_t)bh * SSEQ * DHH;
    const float* Vbh = g_v + (size_t)bh * SSEQ * DHH;
    const int nT = (L + 63) >> 6;

    prefetch_tile(Kbh, Vbh, idx, 0, L, ks_byte, vs_byte, tid);

    // Load Q tile (256 x 64) as tf32 (overlaps with cp.async flight)
    const float* Qg = g_q + ((size_t)bh * SSEQ + q0) * DHH;
    #pragma unroll
    for (int it = 0; it < 16; it++) {
        const int i = tid + it * 256;
        const int r = i >> 4, c4 = (i & 15) << 2;
        const float4 v = *(const float4*)(Qg + r * DHH + c4);
        uint32_t* p = Qs + r * QST + c4;
        p[0] = f2tf32(v.x); p[1] = f2tf32(v.y);
        p[2] = f2tf32(v.z); p[3] = f2tf32(v.w);
    }

    float o[2][8][4] = {};
    float mrow[2][2], lrow[2][2];
    mrow[0][0] = mrow[0][1] = mrow[1][0] = mrow[1][1] = -3.0e38f;
    lrow[0][0] = lrow[0][1] = lrow[1][0] = lrow[1][1] = 0.f;
    const float C = 0.18033688f;   // (1/sqrt(64)) * log2(e)
    const int base = wid << 5;     // warp's first q-row (32 rows per warp)

    for (int t = 0; t < nT; t++) {
        asm volatile("cp.async.wait_group 0;" ::: "memory");   // tile t landed
        __syncthreads();
        if (t + 1 < nT)
            prefetch_tile(Kbh, Vbh, idx, t + 1, L, ks_byte, vs_byte, tid);

        const uint32_t* Kc = KsB + (t & 1) * 64 * KST;
        const uint32_t* Vc = VsB + (t & 1) * 64 * VST;
        const int k0 = t << 6;

        // S = Q K^T  (per warp: 32 rows x 64 keys; B frags shared by 2 blocks)
        float s[2][8][4] = {};
        #pragma unroll
        for (int ks = 0; ks < 8; ks++) {
            uint32_t a[2][4];
            #pragma unroll
            for (int mf = 0; mf < 2; mf++) {
                const uint32_t* pa = Qs + (base + mf*16 + lr) * QST + ks*8 + lc;
                a[mf][0] = pa[0];
                a[mf][1] = pa[8*QST];
                a[mf][2] = pa[4];
                a[mf][3] = pa[8*QST + 4];
            }
            #pragma unroll
            for (int nf = 0; nf < 8; nf++) {
                uint32_t b[2];
                const uint32_t* pb = Kc + (nf*8 + lr) * KST + ks*8 + lc;
                b[0] = pb[0];
                b[1] = pb[4];
                mma_tf32(s[0][nf], a[0], b);
                mma_tf32(s[1][nf], a[1], b);
            }
        }

        // Scale + mask padding columns
        #pragma unroll
        for (int nf = 0; nf < 8; nf++) {
            const int cb = k0 + nf*8 + 2*lc;
            const bool v0 = cb < L, v1 = (cb + 1) < L;
            #pragma unroll
            for (int mf = 0; mf < 2; mf++) {
                s[mf][nf][0] = v0 ? s[mf][nf][0]*C : -3.0e38f;
                s[mf][nf][1] = v1 ? s[mf][nf][1]*C : -3.0e38f;
                s[mf][nf][2] = v0 ? s[mf][nf][2]*C : -3.0e38f;
                s[mf][nf][3] = v1 ? s[mf][nf][3]*C : -3.0e38f;
            }
        }

        // Online softmax per row block
        #pragma unroll
        for (int mf = 0; mf < 2; mf++) {
            float pm0 = -3.0e38f, pm1 = -3.0e38f;
            #pragma unroll
            for (int nf = 0; nf < 8; nf++) {
                pm0 = fmaxf(pm0, fmaxf(s[mf][nf][0], s[mf][nf][1]));
                pm1 = fmaxf(pm1, fmaxf(s[mf][nf][2], s[mf][nf][3]));
            }
            pm0 = fmaxf(pm0, __shfl_xor_sync(0xffffffffu, pm0, 1));
            pm0 = fmaxf(pm0, __shfl_xor_sync(0xffffffffu, pm0, 2));
            pm1 = fmaxf(pm1, __shfl_xor_sync(0xffffffffu, pm1, 1));
            pm1 = fmaxf(pm1, __shfl_xor_sync(0xffffffffu, pm1, 2));

            const float mn0 = fmaxf(mrow[mf][0], pm0);
            const float mn1 = fmaxf(mrow[mf][1], pm1);
            const float al0 = fexp2(mrow[mf][0] - mn0);
            const float al1 = fexp2(mrow[mf][1] - mn1);
            mrow[mf][0] = mn0; mrow[mf][1] = mn1;

            float sum0 = 0.f, sum1 = 0.f;
            uint32_t* Pw0 = Ps + (base + mf*16 + lr) * QST + 2*lc;
            uint32_t* Pw1 = Pw0 + 8*QST;
            #pragma unroll
            for (int nf = 0; nf < 8; nf++) {
                const float p0 = fexp2(s[mf][nf][0] - mn0);
                const float p1 = fexp2(s[mf][nf][1] - mn0);
                const float p2 = fexp2(s[mf][nf][2] - mn1);
                const float p3 = fexp2(s[mf][nf][3] - mn1);
                sum0 += p0 + p1;
                sum1 += p2 + p3;
                Pw0[nf*8 + 0] = f2tf32(p0);
                Pw0[nf*8 + 1] = f2tf32(p1);
                Pw1[nf*8 + 0] = f2tf32(p2);
                Pw1[nf*8 + 1] = f2tf32(p3);
            }
            sum0 += __shfl_xor_sync(0xffffffffu, sum0, 1);
            sum0 += __shfl_xor_sync(0xffffffffu, sum0, 2);
            sum1 += __shfl_xor_sync(0xffffffffu, sum1, 1);
            sum1 += __shfl_xor_sync(0xffffffffu, sum1, 2);
            lrow[mf][0] = lrow[mf][0] * al0 + sum0;
            lrow[mf][1] = lrow[mf][1] * al1 + sum1;

            #pragma unroll
            for (int nf = 0; nf < 8; nf++) {
                o[mf][nf][0] *= al0; o[mf][nf][1] *= al0;
                o[mf][nf][2] *= al1; o[mf][nf][3] *= al1;
            }
        }
        __syncwarp();   // P written by this warp, read by this warp's lanes

        // O += P V   (B frags from Vc[key][dh], shared by 2 row blocks)
        #pragma unroll
        for (int ks = 0; ks < 8; ks++) {
            uint32_t a[2][4];
            #pragma unroll
            for (int mf = 0; mf < 2; mf++) {
                const uint32_t* pa = Ps + (base + mf*16 + lr) * QST + ks*8 + lc;
                a[mf][0] = pa[0];
                a[mf][1] = pa[8*QST];
                a[mf][2] = pa[4];
                a[mf][3] = pa[8*QST + 4];
            }
            #pragma unroll
            for (int nf = 0; nf < 8; nf++) {
                uint32_t b[2];
                const uint32_t* pb = Vc + (ks*8 + lc) * VST + nf*8 + lr;
                b[0] = pb[0];
                b[1] = pb[4*VST];
                mma_tf32(o[0][nf], a[0], b);
                mma_tf32(o[1][nf], a[1], b);
            }
        }
        // no trailing barrier: next iteration's wait+sync protects buffer reuse
    }

    // Epilogue: normalize and write [b,s,d]
    #pragma unroll
    for (int mf = 0; mf < 2; mf++) {
        const float inv0 = 1.f / lrow[mf][0], inv1 = 1.f / lrow[mf][1];
        const int s0 = q0 + base + mf*16 + lr, s1 = s0 + 8;
        float* d0 = g_attn + ((size_t)bI * SSEQ + s0) * DD + h * DHH + 2*lc;
        float* d1 = g_attn + ((size_t)bI * SSEQ + s1) * DD + h * DHH + 2*lc;
        #pragma unroll
        for (int nf = 0; nf < 8; nf++) {
            float2 w0, w1;
            w0.x = o[mf][nf][0] * inv0; w0.y = o[mf][nf][1] * inv0;
            w1.x = o[mf][nf][2] * inv1; w1.y = o[mf][nf][3] * inv1;
            *(float2*)(d0 + nf*8) = w0;
            *(float2*)(d1 + nf*8) = w1;
        }
    }
}

// ---------------------------------------------------------------------------
extern "C" void kernel_launch(void* const* d_in, const int* in_sizes, int n_in,
                              void* d_out, int out_size) {
    const float* x    = (const float*)d_in[0];
    const int*   mask = (const int*)  d_in[1];
    const float* Wqkv = (const float*)d_in[2];
    const float* bqkv = (const float*)d_in[3];
    const float* Wo   = (const float*)d_in[4];
    const float* bo   = (const float*)d_in[5];
    float* out = (float*)d_out;

    const int attn_smem = (512*QST + 2*64*KST + 2*64*VST) * (int)sizeof(uint32_t);
    cudaFuncSetAttribute(attn_mma, cudaFuncAttributeMaxDynamicSharedMemorySize,
                         attn_smem);
    cudaFuncSetAttribute(qkv_mma, cudaFuncAttributeMaxDynamicSharedMemorySize,
                         GEMM_SMEM_BYTES);
    cudaFuncSetAttribute(out_mma, cudaFuncAttributeMaxDynamicSharedMemorySize,
                         GEMM_SMEM_BYTES);

    qkv_mma<<<dim3(E3/128, (BB*SSEQ)/128), 256, GEMM_SMEM_BYTES>>>(x, Wqkv, bqkv, mask);
    attn_mma<<<dim3(BB*HH, SSEQ/256), 256, attn_smem>>>();
    out_mma<<<dim3(DD/128, (BB*SSEQ)/128), 256, GEMM_SMEM_BYTES>>>(Wo, bo, out);
}

// round 16
// speedup vs baseline: 1.8689x; 1.2099x over previous
#include <cuda_runtime.h>
#include <cuda_fp16.h>
#include <math.h>
#include <stdint.h>

#define BB   4
#define SSEQ 2048
#define DD   512
#define HH   8
#define DHH  64
#define E3   1536

// Scratch (allocation-free rule: __device__ globals)
__device__ __half g_qh[BB*HH*SSEQ*DHH];  // [b,h,s,dh] fp16
__device__ __half g_kh[BB*HH*SSEQ*DHH];
__device__ __half g_vh[BB*HH*SSEQ*DHH];
__device__ float  g_attn[BB*SSEQ*DD];    // [b,s,d]
__device__ int    g_cnt[BB];             // active-key count per batch
__device__ int    g_idx[BB*SSEQ];        // active key indices (unordered)

// ---------------------------------------------------------------------------
// mma.sync helpers (plain sm_80+ PTX)
// ---------------------------------------------------------------------------
// Register-time round-to-nearest for raw fp32 bits fed to tf32 MMA.
#define RNA(x) ((x) + 0x1000u)

__device__ __forceinline__ void mma_tf32(float (&d)[4], const uint32_t (&a)[4],
                                         const uint32_t (&b)[2]) {
    asm volatile("mma.sync.aligned.m16n8k8.row.col.f32.tf32.tf32.f32 "
                 "{%0,%1,%2,%3}, {%4,%5,%6,%7}, {%8,%9}, {%0,%1,%2,%3};"
                 : "+f"(d[0]), "+f"(d[1]), "+f"(d[2]), "+f"(d[3])
                 : "r"(a[0]), "r"(a[1]), "r"(a[2]), "r"(a[3]),
                   "r"(b[0]), "r"(b[1]));
}
__device__ __forceinline__ void mma_f16(float (&d)[4], const uint32_t (&a)[4],
                                        const uint32_t (&b)[2]) {
    asm volatile("mma.sync.aligned.m16n8k16.row.col.f32.f16.f16.f32 "
                 "{%0,%1,%2,%3}, {%4,%5,%6,%7}, {%8,%9}, {%0,%1,%2,%3};"
                 : "+f"(d[0]), "+f"(d[1]), "+f"(d[2]), "+f"(d[3])
                 : "r"(a[0]), "r"(a[1]), "r"(a[2]), "r"(a[3]),
                   "r"(b[0]), "r"(b[1]));
}
__device__ __forceinline__ uint32_t smem_u32(const void* p) {
    uint32_t a;
    asm("{ .reg .u64 t; cvta.to.shared.u64 t, %1; cvt.u32.u64 %0, t; }"
        : "=r"(a) : "l"(p));
    return a;
}
__device__ __forceinline__ uint32_t pack_h2(float lo, float hi) {
    __half2 h = __floats2half2_rn(lo, hi);
    return *reinterpret_cast<uint32_t*>(&h);
}

// Fast 2^x for x <= 0 on the FMA pipe (no MUFU). Rel err ~4e-5.
__device__ __forceinline__ float fexp2(float x) {
    x = fmaxf(x, -126.0f);
    const float z = x + 12582912.0f;                       // 1.5*2^23
    const int   n = (__float_as_int(z) & 0x7FFFFF) - 0x400000;
    const float f = x - (z - 12582912.0f);
    float p = fmaf(fmaf(fmaf(fmaf(0.00961813f, f, 0.05550411f),
                             f, 0.24022651f), f, 0.69314718f), f, 1.0f);
    return __int_as_float(__float_as_int(p) + (n << 23));
}

// ---------------------------------------------------------------------------
// Projection GEMMs (tf32, proven): 128x128 CTA tile, 8 warps, warp tile 64x32.
// cp.async 3-stage pipeline, ONE barrier per chunk.
// ---------------------------------------------------------------------------
#define GST 36
#define KC  32
#define NCH (DD/KC)          // 16 chunks
#define NST 3
#define GEMM_TILE_U32 (128*GST)
#define GEMM_SMEM_BYTES (NST * 2 * GEMM_TILE_U32 * 4)   // 110592

__device__ __forceinline__ void gemm_prefetch(const float* __restrict__ Ag,
                                              const float* __restrict__ Bg,
                                              int ch, uint32_t a_byte,
                                              uint32_t b_byte, int tid) {
    const uint32_t so = (uint32_t)((ch % NST) * 2 * GEMM_TILE_U32 * 4);
    #pragma unroll
    for (int it = 0; it < 4; it++) {
        const int i = tid + it * 256;
        const int r = i >> 3;
        const int c = (i & 7) * 16;
        const void* ga = (const char*)(Ag + (size_t)r * DD + ch * KC) + c;
        const void* gb = (const char*)(Bg + (size_t)r * DD + ch * KC) + c;
        const uint32_t da = a_byte + so + (uint32_t)r * (GST*4) + c;
        const uint32_t db = b_byte + so + (uint32_t)r * (GST*4) + c;
        asm volatile("cp.async.cg.shared.global [%0], [%1], 16;" :: "r"(da), "l"(ga));
        asm volatile("cp.async.cg.shared.global [%0], [%1], 16;" :: "r"(db), "l"(gb));
    }
    asm volatile("cp.async.commit_group;" ::: "memory");
}

__device__ __forceinline__ void mma_mainloop(const float* __restrict__ Ag,
                                             const float* __restrict__ Bg,
                                             uint32_t* smu,
                                             float acc[4][4][4]) {
    const int tid = threadIdx.x;
    const int wid = tid >> 5, lane = tid & 31;
    const int wm = wid >> 2, wn = wid & 3;
    const int lr = lane >> 2, lc = lane & 3;
    const uint32_t sb = smem_u32(smu);
    const uint32_t a_byte = sb;
    const uint32_t b_byte = sb + GEMM_TILE_U32 * 4;

    gemm_prefetch(Ag, Bg, 0, a_byte, b_byte, tid);
    gemm_prefetch(Ag, Bg, 1, a_byte, b_byte, tid);

    for (int ch = 0; ch < NCH; ch++) {
        asm volatile("cp.async.wait_group 1;" ::: "memory");
        __syncthreads();
        if (ch + 2 < NCH)
            gemm_prefetch(Ag, Bg, ch + 2, a_byte, b_byte, tid);
        else
            asm volatile("cp.async.commit_group;" ::: "memory");

        const uint32_t* As = smu + (ch % NST) * 2 * GEMM_TILE_U32;
        const uint32_t* Bs = As + GEMM_TILE_U32;

        #pragma unroll
        for (int ks = 0; ks < KC; ks += 8) {
            uint32_t a[4][4], b[4][2];
            #pragma unroll
            for (int mf = 0; mf < 4; mf++) {
                const uint32_t* p = As + (wm*64 + mf*16 + lr) * GST + ks + lc;
                a[mf][0] = RNA(p[0]);
                a[mf][1] = RNA(p[8*GST]);
                a[mf][2] = RNA(p[4]);
                a[mf][3] = RNA(p[8*GST + 4]);
            }
            #pragma unroll
            for (int nf = 0; nf < 4; nf++) {
                const uint32_t* p = Bs + (wn*32 + nf*8 + lr) * GST + ks + lc;
                b[nf][0] = RNA(p[0]);
                b[nf][1] = RNA(p[4]);
            }
            #pragma unroll
            for (int mf = 0; mf < 4; mf++)
                #pragma unroll
                for (int nf = 0; nf < 4; nf++)
                    mma_tf32(acc[mf][nf], a[mf], b[nf]);
        }
    }
}

__global__ __launch_bounds__(256, 2) void qkv_mma(const float* __restrict__ X,
                                                  const float* __restrict__ W,
                                                  const float* __restrict__ bias,
                                                  const int* __restrict__ mask) {
    extern __shared__ uint32_t smu[];
    // Fused mask compaction (exact: softmax order-invariant; dropped keys
    // carry weight exp(NEG - max) == 0).
    if (blockIdx.x == 0 && blockIdx.y < BB) {
        const int b = blockIdx.y;
        if (threadIdx.x == 0) g_cnt[b] = 0;
        __syncthreads();
        #pragma unroll
        for (int i = threadIdx.x; i < SSEQ; i += 256) {
            if (mask[b * SSEQ + i] != 0) {
                const int p = atomicAdd(&g_cnt[b], 1);
                g_idx[b * SSEQ + p] = i;
            }
        }
    }

    const int m0 = blockIdx.y << 7, n0 = blockIdx.x << 7;
    float acc[4][4][4] = {};
    mma_mainloop(X + (size_t)m0 * DD, W + (size_t)n0 * DD, smu, acc);

    const int tid = threadIdx.x;
    const int wid = tid >> 5, lane = tid & 31;
    const int wm = wid >> 2, wn = wid & 3;
    const int lr = lane >> 2, lc = lane & 3;

    #pragma unroll
    for (int mf = 0; mf < 4; mf++) {
        #pragma unroll
        for (int nf = 0; nf < 4; nf++) {
            const int cb = n0 + wn*32 + nf*8 + 2*lc;     // even
            const int h   = cb / 192;
            const int rr  = cb - h * 192;
            const int sel = rr >> 6;
            const int dh0 = rr & 63;                     // even
            __half* gbase = (sel == 0 ? g_qh : sel == 1 ? g_kh : g_vh);
            const float b0 = bias[cb], b1 = bias[cb + 1];
            #pragma unroll
            for (int half_i = 0; half_i < 2; half_i++) {
                const int row = m0 + wm*64 + mf*16 + lr + 8*half_i;
                const int bI = row >> 11, sI = row & (SSEQ - 1);
                __half2 hv = __floats2half2_rn(acc[mf][nf][2*half_i + 0] + b0,
                                               acc[mf][nf][2*half_i + 1] + b1);
                *(__half2*)(gbase + ((size_t)(bI*HH + h)*SSEQ + sI)*DHH + dh0) = hv;
            }
        }
    }
}

__global__ __launch_bounds__(256, 2) void out_mma(const float* __restrict__ W,
                                                  const float* __restrict__ bias,
                                                  float* __restrict__ Out) {
    extern __shared__ uint32_t smu[];
    const int m0 = blockIdx.y << 7, n0 = blockIdx.x << 7;
    float acc[4][4][4] = {};
    mma_mainloop(g_attn + (size_t)m0 * DD, W + (size_t)n0 * DD, smu, acc);

    const int tid = threadIdx.x;
    const int wid = tid >> 5, lane = tid & 31;
    const int wm = wid >> 2, wn = wid & 3;
    const int lr = lane >> 2, lc = lane & 3;

    #pragma unroll
    for (int mf = 0; mf < 4; mf++) {
        #pragma unroll
        for (int nf = 0; nf < 4; nf++) {
            const int cb = n0 + wn*32 + nf*8 + 2*lc;
            const float b0 = bias[cb], b1 = bias[cb + 1];
            #pragma unroll
            for (int half_i = 0; half_i < 2; half_i++) {
                const int row = m0 + wm*64 + mf*16 + lr + 8*half_i;
                float2 o;
                o.x = acc[mf][nf][2*half_i + 0] + b0;
                o.y = acc[mf][nf][2*half_i + 1] + b1;
                *(float2*)(Out + (size_t)row * DD + cb) = o;
            }
        }
    }
}

// ---------------------------------------------------------------------------
// Kernel 2: flash attention, fp16 mma m16n8k16.
// - Q/K/V in gmem as fp16 [b,h,s,dh]; rows = 128 B -> cp.async gather works.
// - P stays in REGISTERS: fp16 A-fragment layout == accumulator layout.
// - V transposed per tile in SMEM (Vf [key][dh] -> Vt [dh][key]).
// CTA = 8 warps x 32 q-rows = 256 q-rows. grid: (B*H = 32, S/256 = 8).
// SMEM strides: 72 halves (= 36 u32) per row -> conflict-free fragments.
// ---------------------------------------------------------------------------
#define AST   72                     // halves per row
#define AST32 36                     // u32 per row
#define ROWB  144                    // bytes per row
#define Q_OFF  0
#define K_OFF  (256*ROWB)            // 36864
#define VF_OFF (K_OFF + 2*64*ROWB)   // 55296
#define VT_OFF (VF_OFF + 2*64*ROWB)  // 73728
#define ATTN_SMEM (VT_OFF + 64*ROWB) // 82944

// Prefetch K and V tiles (fp16, gathered rows of 128 B) into buf t&1.
__device__ __forceinline__ void prefetch_kv(const __half* Kbh, const __half* Vbh,
                                            const int* idx, int t, int L,
                                            uint32_t sb, int tid) {
    const uint32_t bo = (uint32_t)((t & 1) * 64 * ROWB);
    #pragma unroll
    for (int it = 0; it < 2; it++) {
        const int i = tid + it * 256;
        const int r = i >> 3;               // key row 0..63
        const int ch = (i & 7) * 16;        // byte chunk within 128B row
        const int rr = (t << 6) + r;
        const int kr = idx[rr < L ? rr : L - 1];
        const void* gk = (const char*)(Kbh + (size_t)kr * DHH) + ch;
        const void* gv = (const char*)(Vbh + (size_t)kr * DHH) + ch;
        const uint32_t dk = sb + K_OFF  + bo + (uint32_t)r * ROWB + ch;
        const uint32_t dv = sb + VF_OFF + bo + (uint32_t)r * ROWB + ch;
        asm volatile("cp.async.cg.shared.global [%0], [%1], 16;" :: "r"(dk), "l"(gk));
        asm volatile("cp.async.cg.shared.global [%0], [%1], 16;" :: "r"(dv), "l"(gv));
    }
    asm volatile("cp.async.commit_group;" ::: "memory");
}

__global__ __launch_bounds__(256) void attn_mma() {
    extern __shared__ uint32_t smu[];
    const uint32_t sb = smem_u32(smu);
    uint32_t* Qs32 = smu;                                  // fp16 Q, u32 view
    uint32_t* Vt32 = (uint32_t*)((char*)smu + VT_OFF);     // fp16 V^T, u32 view

    const int tid = threadIdx.x;
    const int wid = tid >> 5, lane = tid & 31;
    const int lr = lane >> 2, lc = lane & 3;
    const int bh = blockIdx.x;
    const int bI = bh >> 3, h = bh & 7;
    const int q0 = blockIdx.y << 8;
    const int L  = g_cnt[bI];
    const int* idx = g_idx + bI * SSEQ;
    const __half* Kbh = g_kh + (size_t)bh * SSEQ * DHH;
    const __half* Vbh = g_vh + (size_t)bh * SSEQ * DHH;
    const int nT = (L + 63) >> 6;

    prefetch_kv(Kbh, Vbh, idx, 0, L, sb, tid);

    // Q tile (256 rows x 128 B) via cp.async
    {
        const char* Qg = (const char*)(g_qh + ((size_t)bh * SSEQ + q0) * DHH);
        #pragma unroll
        for (int it = 0; it < 8; it++) {
            const int i = tid + it * 256;
            const int r = i >> 3;
            const int ch = (i & 7) * 16;
            const uint32_t dq = sb + Q_OFF + (uint32_t)r * ROWB + ch;
            asm volatile("cp.async.cg.shared.global [%0], [%1], 16;"
                         :: "r"(dq), "l"(Qg + (size_t)r * 128 + ch));
        }
        asm volatile("cp.async.commit_group;" ::: "memory");
    }

    float o[2][8][4] = {};
    float mrow[2][2], lrow[2][2];
    mrow[0][0] = mrow[0][1] = mrow[1][0] = mrow[1][1] = -3.0e38f;
    lrow[0][0] = lrow[0][1] = lrow[1][0] = lrow[1][1] = 0.f;
    const float C = 0.18033688f;   // (1/sqrt(64)) * log2(e)
    const int base = wid << 5;     // warp's first q-row

    for (int t = 0; t < nT; t++) {
        asm volatile("cp.async.wait_group 0;" ::: "memory");   // tile t (+Q) landed
        __syncthreads();
        if (t + 1 < nT)
            prefetch_kv(Kbh, Vbh, idx, t + 1, L, sb, tid);

        const uint32_t* Kc = (const uint32_t*)((char*)smu + K_OFF + (t & 1) * 64 * ROWB);
        const int k0 = t << 6;

        // S = Q K^T  (fp16 k16; per warp 32 rows x 64 keys)
        float s[2][8][4] = {};
        #pragma unroll
        for (int ks = 0; ks < 4; ks++) {
            uint32_t a[2][4];
            #pragma unroll
            for (int mf = 0; mf < 2; mf++) {
                const uint32_t* pa = Qs32 + (base + mf*16 + lr) * AST32 + ks*8 + lc;
                a[mf][0] = pa[0];
                a[mf][1] = pa[8*AST32];
                a[mf][2] = pa[4];
                a[mf][3] = pa[8*AST32 + 4];
            }
            #pragma unroll
            for (int nf = 0; nf < 8; nf++) {
                uint32_t b[2];
                const uint32_t* pb = Kc + (nf*8 + lr) * AST32 + ks*8 + lc;
                b[0] = pb[0];
                b[1] = pb[4];
                mma_f16(s[0][nf], a[0], b);
                mma_f16(s[1][nf], a[1], b);
            }
        }

        // Transpose V tile: Vf[key][dh] -> Vt[dh][key] (half2 pairs of keys)
        {
            const __half* Vfh = (const __half*)((char*)smu + VF_OFF + (t & 1) * 64 * ROWB);
            const int dh = tid & 63, kpg = tid >> 6;
            #pragma unroll
            for (int j = 0; j < 8; j++) {
                const int kp = kpg * 8 + j;
                const __half h0 = Vfh[(2*kp    ) * AST + dh];
                const __half h1 = Vfh[(2*kp + 1) * AST + dh];
                __half2 hh = __halves2half2(h0, h1);
                Vt32[dh * AST32 + kp] = *reinterpret_cast<uint32_t*>(&hh);
            }
        }

        // Scale + mask padding columns
        #pragma unroll
        for (int nf = 0; nf < 8; nf++) {
            const int cb = k0 + nf*8 + 2*lc;
            const bool v0 = cb < L, v1 = (cb + 1) < L;
            #pragma unroll
            for (int mf = 0; mf < 2; mf++) {
                s[mf][nf][0] = v0 ? s[mf][nf][0]*C : -3.0e38f;
                s[mf][nf][1] = v1 ? s[mf][nf][1]*C : -3.0e38f;
                s[mf][nf][2] = v0 ? s[mf][nf][2]*C : -3.0e38f;
                s[mf][nf][3] = v1 ? s[mf][nf][3]*C : -3.0e38f;
            }
        }

        // Online softmax; pack P into fp16 A-fragments (registers only)
        uint32_t paL[2][8], paH[2][8];
        #pragma unroll
        for (int mf = 0; mf < 2; mf++) {
            float pm0 = -3.0e38f, pm1 = -3.0e38f;
            #pragma unroll
            for (int nf = 0; nf < 8; nf++) {
                pm0 = fmaxf(pm0, fmaxf(s[mf][nf][0], s[mf][nf][1]));
                pm1 = fmaxf(pm1, fmaxf(s[mf][nf][2], s[mf][nf][3]));
            }
            pm0 = fmaxf(pm0, __shfl_xor_sync(0xffffffffu, pm0, 1));
            pm0 = fmaxf(pm0, __shfl_xor_sync(0xffffffffu, pm0, 2));
            pm1 = fmaxf(pm1, __shfl_xor_sync(0xffffffffu, pm1, 1));
            pm1 = fmaxf(pm1, __shfl_xor_sync(0xffffffffu, pm1, 2));

            const float mn0 = fmaxf(mrow[mf][0], pm0);
            const float mn1 = fmaxf(mrow[mf][1], pm1);
            const float al0 = fexp2(mrow[mf][0] - mn0);
            const float al1 = fexp2(mrow[mf][1] - mn1);
            mrow[mf][0] = mn0; mrow[mf][1] = mn1;

            float sum0 = 0.f, sum1 = 0.f;
            #pragma unroll
            for (int nf = 0; nf < 8; nf++) {
                const float p0 = fexp2(s[mf][nf][0] - mn0);
                const float p1 = fexp2(s[mf][nf][1] - mn0);
                const float p2 = fexp2(s[mf][nf][2] - mn1);
                const float p3 = fexp2(s[mf][nf][3] - mn1);
                sum0 += p0 + p1;
                sum1 += p2 + p3;
                paL[mf][nf] = pack_h2(p0, p1);
                paH[mf][nf] = pack_h2(p2, p3);
            }
            sum0 += __shfl_xor_sync(0xffffffffu, sum0, 1);
            sum0 += __shfl_xor_sync(0xffffffffu, sum0, 2);
            sum1 += __shfl_xor_sync(0xffffffffu, sum1, 1);
            sum1 += __shfl_xor_sync(0xffffffffu, sum1, 2);
            lrow[mf][0] = lrow[mf][0] * al0 + sum0;
            lrow[mf][1] = lrow[mf][1] * al1 + sum1;

            #pragma unroll
            for (int nf = 0; nf < 8; nf++) {
                o[mf][nf][0] *= al0; o[mf][nf][1] *= al0;
                o[mf][nf][2] *= al1; o[mf][nf][3] *= al1;
            }
        }
        __syncthreads();   // Vt writes visible to all warps before PV

        // O += P V  (A = packed P regs; B = Vt fragments)
        #pragma unroll
        for (int ks = 0; ks < 4; ks++) {
            uint32_t a[2][4];
            #pragma unroll
            for (int mf = 0; mf < 2; mf++) {
                a[mf][0] = paL[mf][2*ks];
                a[mf][1] = paH[mf][2*ks];
                a[mf][2] = paL[mf][2*ks + 1];
                a[mf][3] = paH[mf][2*ks + 1];
            }
            #pragma unroll
            for (int nf = 0; nf < 8; nf++) {
                uint32_t b[2];
                const uint32_t* pb = Vt32 + (nf*8 + lr) * AST32 + ks*8 + lc;
                b[0] = pb[0];
                b[1] = pb[4];
                mma_f16(o[0][nf], a[0], b);
                mma_f16(o[1][nf], a[1], b);
            }
        }
        // next iteration's wait+sync protects K/Vf buffer reuse; Vt is
        // rewritten only after that same sync.
    }

    // Epilogue: normalize and write [b,s,d]
    #pragma unroll
    for (int mf = 0; mf < 2; mf++) {
        const float inv0 = 1.f / lrow[mf][0], inv1 = 1.f / lrow[mf][1];
        const int s0 = q0 + base + mf*16 + lr, s1 = s0 + 8;
        float* d0 = g_attn + ((size_t)bI * SSEQ + s0) * DD + h * DHH + 2*lc;
        float* d1 = g_attn + ((size_t)bI * SSEQ + s1) * DD + h * DHH + 2*lc;
        #pragma unroll
        for (int nf = 0; nf < 8; nf++) {
            float2 w0, w1;
            w0.x = o[mf][nf][0] * inv0; w0.y = o[mf][nf][1] * inv0;
            w1.x = o[mf][nf][2] * inv1; w1.y = o[mf][nf][3] * inv1;
            *(float2*)(d0 + nf*8) = w0;
            *(float2*)(d1 + nf*8) = w1;
        }
    }
}

// ---------------------------------------------------------------------------
extern "C" void kernel_launch(void* const* d_in, const int* in_sizes, int n_in,
                              void* d_out, int out_size) {
    const float* x    = (const float*)d_in[0];
    const int*   mask = (const int*)  d_in[1];
    const float* Wqkv = (const float*)d_in[2];
    const float* bqkv = (const float*)d_in[3];
    const float* Wo   = (const float*)d_in[4];
    const float* bo   = (const float*)d_in[5];
    float* out = (float*)d_out;

    cudaFuncSetAttribute(attn_mma, cudaFuncAttributeMaxDynamicSharedMemorySize,
                         ATTN_SMEM);
    cudaFuncSetAttribute(qkv_mma, cudaFuncAttributeMaxDynamicSharedMemorySize,
                         GEMM_SMEM_BYTES);
    cudaFuncSetAttribute(out_mma, cudaFuncAttributeMaxDynamicSharedMemorySize,
                         GEMM_SMEM_BYTES);

    qkv_mma<<<dim3(E3/128, (BB*SSEQ)/128), 256, GEMM_SMEM_BYTES>>>(x, Wqkv, bqkv, mask);
    attn_mma<<<dim3(BB*HH, SSEQ/256), 256, ATTN_SMEM>>>();
    out_mma<<<dim3(DD/128, (BB*SSEQ)/128), 256, GEMM_SMEM_BYTES>>>(Wo, bo, out);
}

// round 17
// speedup vs baseline: 2.3324x; 1.2480x over previous
#include <cuda_runtime.h>
#include <cuda_fp16.h>
#include <math.h>
#include <stdint.h>

#define BB   4
#define SSEQ 2048
#define DD   512
#define HH   8
#define DHH  64
#define E3   1536
#define XN   (BB*SSEQ*DD)      // 4194304
#define WQN  (E3*DD)           // 786432
#define WON  (DD*DD)           // 262144

// Scratch (allocation-free rule: __device__ globals)
__device__ __half g_xh[XN];              // X in fp16
__device__ __half g_wqh[WQN];            // W_qkv in fp16
__device__ __half g_woh[WON];            // W_o in fp16
__device__ __half g_qh[BB*HH*SSEQ*DHH];  // [b,h,s,dh] fp16
__device__ __half g_kh[BB*HH*SSEQ*DHH];
__device__ __half g_vh[BB*HH*SSEQ*DHH];
__device__ __half g_attnh[XN];           // attention output [b,s,d] fp16
__device__ int    g_cnt[BB];             // active-key count per batch
__device__ int    g_idx[BB*SSEQ];        // active key indices (unordered)

// ---------------------------------------------------------------------------
// mma.sync helpers (plain sm_80+ PTX)
// ---------------------------------------------------------------------------
__device__ __forceinline__ void mma_f16(float (&d)[4], const uint32_t (&a)[4],
                                        const uint32_t (&b)[2]) {
    asm volatile("mma.sync.aligned.m16n8k16.row.col.f32.f16.f16.f32 "
                 "{%0,%1,%2,%3}, {%4,%5,%6,%7}, {%8,%9}, {%0,%1,%2,%3};"
                 : "+f"(d[0]), "+f"(d[1]), "+f"(d[2]), "+f"(d[3])
                 : "r"(a[0]), "r"(a[1]), "r"(a[2]), "r"(a[3]),
                   "r"(b[0]), "r"(b[1]));
}
__device__ __forceinline__ uint32_t smem_u32(const void* p) {
    uint32_t a;
    asm("{ .reg .u64 t; cvta.to.shared.u64 t, %1; cvt.u32.u64 %0, t; }"
        : "=r"(a) : "l"(p));
    return a;
}
__device__ __forceinline__ uint32_t pack_h2(float lo, float hi) {
    __half2 h = __floats2half2_rn(lo, hi);
    return *reinterpret_cast<uint32_t*>(&h);
}

// Fast 2^x for x <= 0 on the FMA pipe (no MUFU). Rel err ~4e-5.
__device__ __forceinline__ float fexp2(float x) {
    x = fmaxf(x, -126.0f);
    const float z = x + 12582912.0f;                       // 1.5*2^23
    const int   n = (__float_as_int(z) & 0x7FFFFF) - 0x400000;
    const float f = x - (z - 12582912.0f);
    float p = fmaf(fmaf(fmaf(fmaf(0.00961813f, f, 0.05550411f),
                             f, 0.24022651f), f, 0.69314718f), f, 1.0f);
    return __int_as_float(__float_as_int(p) + (n << 23));
}

// ---------------------------------------------------------------------------
// Conversion pass: fp32 inputs -> fp16 (RN; mantissa identical to tf32).
// ---------------------------------------------------------------------------
__global__ __launch_bounds__(256) void cvt_all(const float* __restrict__ X,
                                               const float* __restrict__ Wq,
                                               const float* __restrict__ Wo) {
    const int tid = blockIdx.x * 256 + threadIdx.x;
    const int stride = gridDim.x * 256;
    for (int i = tid; i < XN/4; i += stride) {
        const float4 v = ((const float4*)X)[i];
        ((uint2*)g_xh)[i] = make_uint2(pack_h2(v.x, v.y), pack_h2(v.z, v.w));
    }
    for (int i = tid; i < WQN/4; i += stride) {
        const float4 v = ((const float4*)Wq)[i];
        ((uint2*)g_wqh)[i] = make_uint2(pack_h2(v.x, v.y), pack_h2(v.z, v.w));
    }
    for (int i = tid; i < WON/4; i += stride) {
        const float4 v = ((const float4*)Wo)[i];
        ((uint2*)g_woh)[i] = make_uint2(pack_h2(v.x, v.y), pack_h2(v.z, v.w));
    }
}

// ---------------------------------------------------------------------------
// fp16 projection GEMMs: 128x128 CTA tile, 8 warps (2M x 4N), warp tile 64x32.
// m16n8k16, k-chunk 64 halves (128B rows), cp.async 3-stage pipeline with one
// barrier per chunk: wait(ch) -> sync -> prefetch(ch+2) -> compute(ch).
// SMEM rows: 72 halves = 36 u32 (pad) -> conflict-free fragment loads
// (pattern proven in the attention QK mainloop).
// ---------------------------------------------------------------------------
#define GST 36               // u32 per SMEM row
#define ROWB 144             // bytes per SMEM row
#define HKC 64               // k-chunk (halves)
#define NCH (DD/HKC)         // 8 chunks
#define NST 3
#define GEMM_TILE_U32 (128*GST)
#define GEMM_SMEM_BYTES (NST * 2 * GEMM_TILE_U32 * 4)   // 110592

__device__ __forceinline__ void gemm_prefetch_h(const __half* __restrict__ Ag,
                                                const __half* __restrict__ Bg,
                                                int ch, uint32_t a_byte,
                                                uint32_t b_byte, int tid) {
    const uint32_t so = (uint32_t)((ch % NST) * 2 * GEMM_TILE_U32 * 4);
    #pragma unroll
    for (int it = 0; it < 4; it++) {
        const int i = tid + it * 256;
        const int r = i >> 3;               // row 0..127
        const int c = (i & 7) * 16;         // byte chunk within 128B row
        const void* ga = (const char*)(Ag + (size_t)r * DD + ch * HKC) + c;
        const void* gb = (const char*)(Bg + (size_t)r * DD + ch * HKC) + c;
        const uint32_t da = a_byte + so + (uint32_t)r * ROWB + c;
        const uint32_t db = b_byte + so + (uint32_t)r * ROWB + c;
        asm volatile("cp.async.cg.shared.global [%0], [%1], 16;" :: "r"(da), "l"(ga));
        asm volatile("cp.async.cg.shared.global [%0], [%1], 16;" :: "r"(db), "l"(gb));
    }
    asm volatile("cp.async.commit_group;" ::: "memory");
}

__device__ __forceinline__ void mma_mainloop_h(const __half* __restrict__ Ag,
                                               const __half* __restrict__ Bg,
                                               uint32_t* smu,
                                               float acc[4][4][4]) {
    const int tid = threadIdx.x;
    const int wid = tid >> 5, lane = tid & 31;
    const int wm = wid >> 2, wn = wid & 3;
    const int lr = lane >> 2, lc = lane & 3;
    const uint32_t sb = smem_u32(smu);
    const uint32_t a_byte = sb;
    const uint32_t b_byte = sb + GEMM_TILE_U32 * 4;

    gemm_prefetch_h(Ag, Bg, 0, a_byte, b_byte, tid);
    gemm_prefetch_h(Ag, Bg, 1, a_byte, b_byte, tid);

    for (int ch = 0; ch < NCH; ch++) {
        asm volatile("cp.async.wait_group 1;" ::: "memory");   // chunk ch landed
        __syncthreads();
        if (ch + 2 < NCH)
            gemm_prefetch_h(Ag, Bg, ch + 2, a_byte, b_byte, tid);
        else
            asm volatile("cp.async.commit_group;" ::: "memory");  // empty group

        const uint32_t* As = smu + (ch % NST) * 2 * GEMM_TILE_U32;
        const uint32_t* Bs = As + GEMM_TILE_U32;

        #pragma unroll
        for (int ks = 0; ks < 4; ks++) {       // 4 x k16 per 64-half chunk
            uint32_t a[4][4], b[4][2];
            #pragma unroll
            for (int mf = 0; mf < 4; mf++) {
                const uint32_t* p = As + (wm*64 + mf*16 + lr) * GST + ks*8 + lc;
                a[mf][0] = p[0];
                a[mf][1] = p[8*GST];
                a[mf][2] = p[4];
                a[mf][3] = p[8*GST + 4];
            }
            #pragma unroll
            for (int nf = 0; nf < 4; nf++) {
                const uint32_t* p = Bs + (wn*32 + nf*8 + lr) * GST + ks*8 + lc;
                b[nf][0] = p[0];
                b[nf][1] = p[4];
            }
            #pragma unroll
            for (int mf = 0; mf < 4; mf++)
                #pragma unroll
                for (int nf = 0; nf < 4; nf++)
                    mma_f16(acc[mf][nf], a[mf], b[nf]);
        }
        // no trailing barrier: next iteration's wait+sync protects stage reuse
    }
}

__global__ __launch_bounds__(256, 2) void qkv_mma(const float* __restrict__ bias,
                                                  const int* __restrict__ mask) {
    extern __shared__ uint32_t smu[];
    // Fused mask compaction (exact: softmax order-invariant; dropped keys
    // carry weight exp(NEG - max) == 0).
    if (blockIdx.x == 0 && blockIdx.y < BB) {
        const int b = blockIdx.y;
        if (threadIdx.x == 0) g_cnt[b] = 0;
        __syncthreads();
        #pragma unroll
        for (int i = threadIdx.x; i < SSEQ; i += 256) {
            if (mask[b * SSEQ + i] != 0) {
                const int p = atomicAdd(&g_cnt[b], 1);
                g_idx[b * SSEQ + p] = i;
            }
        }
    }

    const int m0 = blockIdx.y << 7, n0 = blockIdx.x << 7;
    float acc[4][4][4] = {};
    mma_mainloop_h(g_xh + (size_t)m0 * DD, g_wqh + (size_t)n0 * DD, smu, acc);

    const int tid = threadIdx.x;
    const int wid = tid >> 5, lane = tid & 31;
    const int wm = wid >> 2, wn = wid & 3;
    const int lr = lane >> 2, lc = lane & 3;

    #pragma unroll
    for (int mf = 0; mf < 4; mf++) {
        #pragma unroll
        for (int nf = 0; nf < 4; nf++) {
            const int cb = n0 + wn*32 + nf*8 + 2*lc;     // even
            const int h   = cb / 192;
            const int rr  = cb - h * 192;
            const int sel = rr >> 6;
            const int dh0 = rr & 63;                     // even
            __half* gbase = (sel == 0 ? g_qh : sel == 1 ? g_kh : g_vh);
            const float b0 = bias[cb], b1 = bias[cb + 1];
            #pragma unroll
            for (int half_i = 0; half_i < 2; half_i++) {
                const int row = m0 + wm*64 + mf*16 + lr + 8*half_i;
                const int bI = row >> 11, sI = row & (SSEQ - 1);
                __half2 hv = __floats2half2_rn(acc[mf][nf][2*half_i + 0] + b0,
                                               acc[mf][nf][2*half_i + 1] + b1);
                *(__half2*)(gbase + ((size_t)(bI*HH + h)*SSEQ + sI)*DHH + dh0) = hv;
            }
        }
    }
}

__global__ __launch_bounds__(256, 2) void out_mma(const float* __restrict__ bias,
                                                  float* __restrict__ Out) {
    extern __shared__ uint32_t smu[];
    const int m0 = blockIdx.y << 7, n0 = blockIdx.x << 7;
    float acc[4][4][4] = {};
    mma_mainloop_h(g_attnh + (size_t)m0 * DD, g_woh + (size_t)n0 * DD, smu, acc);

    const int tid = threadIdx.x;
    const int wid = tid >> 5, lane = tid & 31;
    const int wm = wid >> 2, wn = wid & 3;
    const int lr = lane >> 2, lc = lane & 3;

    #pragma unroll
    for (int mf = 0; mf < 4; mf++) {
        #pragma unroll
        for (int nf = 0; nf < 4; nf++) {
            const int cb = n0 + wn*32 + nf*8 + 2*lc;
            const float b0 = bias[cb], b1 = bias[cb + 1];
            #pragma unroll
            for (int half_i = 0; half_i < 2; half_i++) {
                const int row = m0 + wm*64 + mf*16 + lr + 8*half_i;
                float2 o;
                o.x = acc[mf][nf][2*half_i + 0] + b0;
                o.y = acc[mf][nf][2*half_i + 1] + b1;
                *(float2*)(Out + (size_t)row * DD + cb) = o;
            }
        }
    }
}

// ---------------------------------------------------------------------------
// Kernel 2: flash attention, fp16 mma m16n8k16 (round-16 proven), epilogue
// now writes fp16 g_attnh. CTA = 8 warps x 32 q-rows. grid: (32, 8).
// ---------------------------------------------------------------------------
#define AST   72                     // halves per row
#define AST32 36                     // u32 per row
#define Q_OFF  0
#define K_OFF  (256*ROWB)            // 36864
#define VF_OFF (K_OFF + 2*64*ROWB)   // 55296
#define VT_OFF (VF_OFF + 2*64*ROWB)  // 73728
#define ATTN_SMEM (VT_OFF + 64*ROWB) // 82944

__device__ __forceinline__ void prefetch_kv(const __half* Kbh, const __half* Vbh,
                                            const int* idx, int t, int L,
                                            uint32_t sb, int tid) {
    const uint32_t bo = (uint32_t)((t & 1) * 64 * ROWB);
    #pragma unroll
    for (int it = 0; it < 2; it++) {
        const int i = tid + it * 256;
        const int r = i >> 3;               // key row 0..63
        const int ch = (i & 7) * 16;        // byte chunk within 128B row
        const int rr = (t << 6) + r;
        const int kr = idx[rr < L ? rr : L - 1];
        const void* gk = (const char*)(Kbh + (size_t)kr * DHH) + ch;
        const void* gv = (const char*)(Vbh + (size_t)kr * DHH) + ch;
        const uint32_t dk = sb + K_OFF  + bo + (uint32_t)r * ROWB + ch;
        const uint32_t dv = sb + VF_OFF + bo + (uint32_t)r * ROWB + ch;
        asm volatile("cp.async.cg.shared.global [%0], [%1], 16;" :: "r"(dk), "l"(gk));
        asm volatile("cp.async.cg.shared.global [%0], [%1], 16;" :: "r"(dv), "l"(gv));
    }
    asm volatile("cp.async.commit_group;" ::: "memory");
}

__global__ __launch_bounds__(256) void attn_mma() {
    extern __shared__ uint32_t smu[];
    const uint32_t sb = smem_u32(smu);
    uint32_t* Qs32 = smu;
    uint32_t* Vt32 = (uint32_t*)((char*)smu + VT_OFF);

    const int tid = threadIdx.x;
    const int wid = tid >> 5, lane = tid & 31;
    const int lr = lane >> 2, lc = lane & 3;
    const int bh = blockIdx.x;
    const int bI = bh >> 3, h = bh & 7;
    const int q0 = blockIdx.y << 8;
    const int L  = g_cnt[bI];
    const int* idx = g_idx + bI * SSEQ;
    const __half* Kbh = g_kh + (size_t)bh * SSEQ * DHH;
    const __half* Vbh = g_vh + (size_t)bh * SSEQ * DHH;
    const int nT = (L + 63) >> 6;

    prefetch_kv(Kbh, Vbh, idx, 0, L, sb, tid);

    // Q tile (256 rows x 128 B) via cp.async
    {
        const char* Qg = (const char*)(g_qh + ((size_t)bh * SSEQ + q0) * DHH);
        #pragma unroll
        for (int it = 0; it < 8; it++) {
            const int i = tid + it * 256;
            const int r = i >> 3;
            const int ch = (i & 7) * 16;
            const uint32_t dq = sb + Q_OFF + (uint32_t)r * ROWB + ch;
            asm volatile("cp.async.cg.shared.global [%0], [%1], 16;"
                         :: "r"(dq), "l"(Qg + (size_t)r * 128 + ch));
        }
        asm volatile("cp.async.commit_group;" ::: "memory");
    }

    float o[2][8][4] = {};
    float mrow[2][2], lrow[2][2];
    mrow[0][0] = mrow[0][1] = mrow[1][0] = mrow[1][1] = -3.0e38f;
    lrow[0][0] = lrow[0][1] = lrow[1][0] = lrow[1][1] = 0.f;
    const float C = 0.18033688f;   // (1/sqrt(64)) * log2(e)
    const int base = wid << 5;

    for (int t = 0; t < nT; t++) {
        asm volatile("cp.async.wait_group 0;" ::: "memory");   // tile t (+Q) landed
        __syncthreads();
        if (t + 1 < nT)
            prefetch_kv(Kbh, Vbh, idx, t + 1, L, sb, tid);

        const uint32_t* Kc = (const uint32_t*)((char*)smu + K_OFF + (t & 1) * 64 * ROWB);
        const int k0 = t << 6;

        // S = Q K^T
        float s[2][8][4] = {};
        #pragma unroll
        for (int ks = 0; ks < 4; ks++) {
            uint32_t a[2][4];
            #pragma unroll
            for (int mf = 0; mf < 2; mf++) {
                const uint32_t* pa = Qs32 + (base + mf*16 + lr) * AST32 + ks*8 + lc;
                a[mf][0] = pa[0];
                a[mf][1] = pa[8*AST32];
                a[mf][2] = pa[4];
                a[mf][3] = pa[8*AST32 + 4];
            }
            #pragma unroll
            for (int nf = 0; nf < 8; nf++) {
                uint32_t b[2];
                const uint32_t* pb = Kc + (nf*8 + lr) * AST32 + ks*8 + lc;
                b[0] = pb[0];
                b[1] = pb[4];
                mma_f16(s[0][nf], a[0], b);
                mma_f16(s[1][nf], a[1], b);
            }
        }

        // Transpose V tile: Vf[key][dh] -> Vt[dh][key]
        {
            const __half* Vfh = (const __half*)((char*)smu + VF_OFF + (t & 1) * 64 * ROWB);
            const int dh = tid & 63, kpg = tid >> 6;
            #pragma unroll
            for (int j = 0; j < 8; j++) {
                const int kp = kpg * 8 + j;
                const __half h0 = Vfh[(2*kp    ) * AST + dh];
                const __half h1 = Vfh[(2*kp + 1) * AST + dh];
                __half2 hh = __halves2half2(h0, h1);
                Vt32[dh * AST32 + kp] = *reinterpret_cast<uint32_t*>(&hh);
            }
        }

        // Scale + mask padding columns
        #pragma unroll
        for (int nf = 0; nf < 8; nf++) {
            const int cb = k0 + nf*8 + 2*lc;
            const bool v0 = cb < L, v1 = (cb + 1) < L;
            #pragma unroll
            for (int mf = 0; mf < 2; mf++) {
                s[mf][nf][0] = v0 ? s[mf][nf][0]*C : -3.0e38f;
                s[mf][nf][1] = v1 ? s[mf][nf][1]*C : -3.0e38f;
                s[mf][nf][2] = v0 ? s[mf][nf][2]*C : -3.0e38f;
                s[mf][nf][3] = v1 ? s[mf][nf][3]*C : -3.0e38f;
            }
        }

        // Online softmax; pack P into fp16 A-fragments (registers only)
        uint32_t paL[2][8], paH[2][8];
        #pragma unroll
        for (int mf = 0; mf < 2; mf++) {
            float pm0 = -3.0e38f, pm1 = -3.0e38f;
            #pragma unroll
            for (int nf = 0; nf < 8; nf++) {
                pm0 = fmaxf(pm0, fmaxf(s[mf][nf][0], s[mf][nf][1]));
                pm1 = fmaxf(pm1, fmaxf(s[mf][nf][2], s[mf][nf][3]));
            }
            pm0 = fmaxf(pm0, __shfl_xor_sync(0xffffffffu, pm0, 1));
            pm0 = fmaxf(pm0, __shfl_xor_sync(0xffffffffu, pm0, 2));
            pm1 = fmaxf(pm1, __shfl_xor_sync(0xffffffffu, pm1, 1));
            pm1 = fmaxf(pm1, __shfl_xor_sync(0xffffffffu, pm1, 2));

            const float mn0 = fmaxf(mrow[mf][0], pm0);
            const float mn1 = fmaxf(mrow[mf][1], pm1);
            const float al0 = fexp2(mrow[mf][0] - mn0);
            const float al1 = fexp2(mrow[mf][1] - mn1);
            mrow[mf][0] = mn0; mrow[mf][1] = mn1;

            float sum0 = 0.f, sum1 = 0.f;
            #pragma unroll
            for (int nf = 0; nf < 8; nf++) {
                const float p0 = fexp2(s[mf][nf][0] - mn0);
                const float p1 = fexp2(s[mf][nf][1] - mn0);
                const float p2 = fexp2(s[mf][nf][2] - mn1);
                const float p3 = fexp2(s[mf][nf][3] - mn1);
                sum0 += p0 + p1;
                sum1 += p2 + p3;
                paL[mf][nf] = pack_h2(p0, p1);
                paH[mf][nf] = pack_h2(p2, p3);
            }
            sum0 += __shfl_xor_sync(0xffffffffu, sum0, 1);
            sum0 += __shfl_xor_sync(0xffffffffu, sum0, 2);
            sum1 += __shfl_xor_sync(0xffffffffu, sum1, 1);
            sum1 += __shfl_xor_sync(0xffffffffu, sum1, 2);
            lrow[mf][0] = lrow[mf][0] * al0 + sum0;
            lrow[mf][1] = lrow[mf][1] * al1 + sum1;

            #pragma unroll
            for (int nf = 0; nf < 8; nf++) {
                o[mf][nf][0] *= al0; o[mf][nf][1] *= al0;
                o[mf][nf][2] *= al1; o[mf][nf][3] *= al1;
            }
        }
        __syncthreads();   // Vt writes visible to all warps before PV

        // O += P V
        #pragma unroll
        for (int ks = 0; ks < 4; ks++) {
            uint32_t a[2][4];
            #pragma unroll
            for (int mf = 0; mf < 2; mf++) {
                a[mf][0] = paL[mf][2*ks];
                a[mf][1] = paH[mf][2*ks];
                a[mf][2] = paL[mf][2*ks + 1];
                a[mf][3] = paH[mf][2*ks + 1];
            }
            #pragma unroll
            for (int nf = 0; nf < 8; nf++) {
                uint32_t b[2];
                const uint32_t* pb = Vt32 + (nf*8 + lr) * AST32 + ks*8 + lc;
                b[0] = pb[0];
                b[1] = pb[4];
                mma_f16(o[0][nf], a[0], b);
                mma_f16(o[1][nf], a[1], b);
            }
        }
        // next iteration's wait+sync protects K/Vf buffer reuse; Vt is
        // rewritten only after that same sync.
    }

    // Epilogue: normalize, write fp16 [b,s,d]
    #pragma unroll
    for (int mf = 0; mf < 2; mf++) {
        const float inv0 = 1.f / lrow[mf][0], inv1 = 1.f / lrow[mf][1];
        const int s0 = q0 + base + mf*16 + lr, s1 = s0 + 8;
        __half* d0 = g_attnh + ((size_t)bI * SSEQ + s0) * DD + h * DHH + 2*lc;
        __half* d1 = g_attnh + ((size_t)bI * SSEQ + s1) * DD + h * DHH + 2*lc;
        #pragma unroll
        for (int nf = 0; nf < 8; nf++) {
            *(__half2*)(d0 + nf*8) = __floats2half2_rn(o[mf][nf][0]*inv0,
                                                       o[mf][nf][1]*inv0);
            *(__half2*)(d1 + nf*8) = __floats2half2_rn(o[mf][nf][2]*inv1,
                                                       o[mf][nf][3]*inv1);
        }
    }
}

// ---------------------------------------------------------------------------
extern "C" void kernel_launch(void* const* d_in, const int* in_sizes, int n_in,
                              void* d_out, int out_size) {
    const float* x    = (const float*)d_in[0];
    const int*   mask = (const int*)  d_in[1];
    const float* Wqkv = (const float*)d_in[2];
    const float* bqkv = (const float*)d_in[3];
    const float* Wo   = (const float*)d_in[4];
    const float* bo   = (const float*)d_in[5];
    float* out = (float*)d_out;

    cudaFuncSetAttribute(attn_mma, cudaFuncAttributeMaxDynamicSharedMemorySize,
                         ATTN_SMEM);
    cudaFuncSetAttribute(qkv_mma, cudaFuncAttributeMaxDynamicSharedMemorySize,
                         GEMM_SMEM_BYTES);
    cudaFuncSetAttribute(out_mma, cudaFuncAttributeMaxDynamicSharedMemorySize,
                         GEMM_SMEM_BYTES);

    cvt_all<<<1024, 256>>>(x, Wqkv, Wo);
    qkv_mma<<<dim3(E3/128, (BB*SSEQ)/128), 256, GEMM_SMEM_BYTES>>>(bqkv, mask);
    attn_mma<<<dim3(BB*HH, SSEQ/256), 256, ATTN_SMEM>>>();
    out_mma<<<dim3(DD/128, (BB*SSEQ)/128), 256, GEMM_SMEM_BYTES>>>(bo, out);
}